// round 1
// baseline (speedup 1.0000x reference)
#include <cuda_runtime.h>

#define B_DIM 16384
#define K_DIM 512
#define T_DIM 16
#define IN_STRIDE 513

// ---------------- device scratch (static allocation is allowed) ----------------
__device__ float g_x[B_DIM * K_DIM];      // packed contiguous x
__device__ float g_lat1[B_DIM * K_DIM];   // relu(x@W1+b1)
__device__ float g_lat2[B_DIM * K_DIM];   // relu(l1@W2+b2)
__device__ int   g_bins[T_DIM * B_DIM];   // row indices per head
__device__ int   g_cnt[T_DIM];            // rows per head

// ---------------- zero counters ----------------
__global__ void k_zero() {
    if (threadIdx.x < T_DIM) g_cnt[threadIdx.x] = 0;
}

// ---------------- pack x contiguous, bin rows by cause, init out with bh2 ----------------
__global__ void k_pack(const float* __restrict__ in, const float* __restrict__ bh2,
                       float* __restrict__ out) {
    int base = blockIdx.x * 8;  // 8 rows per block
    for (int i = threadIdx.x; i < 8 * K_DIM; i += blockDim.x) {
        int r = i >> 9;
        int c = i & 511;
        g_x[(base + r) * K_DIM + c] = in[(base + r) * IN_STRIDE + c];
    }
    if (threadIdx.x < 8) {
        int b = base + threadIdx.x;
        int t = (int)in[b * IN_STRIDE + K_DIM];
        int pos = atomicAdd(&g_cnt[t], 1);
        g_bins[t * B_DIM + pos] = b;
        out[b] = bh2[t];
    }
}

// ---------------- fused GEMM + bias + relu: C[M,512] = relu(A[M,512] @ W[512,512] + bias) ----------------
// 128x128 tile, BK=8, double-buffered, 256 threads, 8x8 per thread.
__global__ void __launch_bounds__(256) k_gemm_relu(
    const float* __restrict__ A, const float* __restrict__ W,
    const float* __restrict__ bias, float* __restrict__ C) {
    __shared__ float As[2][8][128];
    __shared__ float Bs[2][8][128];

    int tid = threadIdx.x;
    int m0 = blockIdx.x * 128;
    int n0 = blockIdx.y * 128;
    int ty = tid >> 4;      // 0..15  rows ty*8..ty*8+7
    int tx = tid & 15;      // 0..15  cols tx*8..tx*8+7

    int arow = tid >> 1;            // 0..127
    int acol = (tid & 1) * 4;       // 0 or 4
    int brow = tid >> 5;            // 0..7
    int bcol = (tid & 31) * 4;      // 0..124

    const float* Aptr = A + (size_t)(m0 + arow) * K_DIM + acol;
    const float* Wptr = W + (size_t)brow * K_DIM + n0 + bcol;

    float acc[8][8];
#pragma unroll
    for (int i = 0; i < 8; i++)
#pragma unroll
        for (int j = 0; j < 8; j++) acc[i][j] = 0.f;

    // prologue: k0 = 0
    float4 av = *(const float4*)(Aptr);
    float4 bv = *(const float4*)(Wptr);
    As[0][acol + 0][arow] = av.x;
    As[0][acol + 1][arow] = av.y;
    As[0][acol + 2][arow] = av.z;
    As[0][acol + 3][arow] = av.w;
    *(float4*)&Bs[0][brow][bcol] = bv;
    __syncthreads();

    int buf = 0;
#pragma unroll 1
    for (int k0 = 0; k0 < K_DIM; k0 += 8) {
        bool last = (k0 + 8 >= K_DIM);
        if (!last) {
            av = *(const float4*)(Aptr + k0 + 8);
            bv = *(const float4*)(Wptr + (size_t)(k0 + 8) * K_DIM);
        }
#pragma unroll
        for (int kk = 0; kk < 8; kk++) {
            float ra[8], rb[8];
#pragma unroll
            for (int i = 0; i < 8; i++) ra[i] = As[buf][kk][ty * 8 + i];
#pragma unroll
            for (int j = 0; j < 8; j++) rb[j] = Bs[buf][kk][tx * 8 + j];
#pragma unroll
            for (int i = 0; i < 8; i++)
#pragma unroll
                for (int j = 0; j < 8; j++) acc[i][j] += ra[i] * rb[j];
        }
        if (!last) {
            int nb = buf ^ 1;
            As[nb][acol + 0][arow] = av.x;
            As[nb][acol + 1][arow] = av.y;
            As[nb][acol + 2][arow] = av.z;
            As[nb][acol + 3][arow] = av.w;
            *(float4*)&Bs[nb][brow][bcol] = bv;
            __syncthreads();
            buf = nb;
        }
    }

    // epilogue: bias + relu, vectorized store
    float bofs[8];
#pragma unroll
    for (int j = 0; j < 8; j++) bofs[j] = bias[n0 + tx * 8 + j];
#pragma unroll
    for (int i = 0; i < 8; i++) {
        int m = m0 + ty * 8 + i;
        float4 v0, v1;
        v0.x = fmaxf(acc[i][0] + bofs[0], 0.f);
        v0.y = fmaxf(acc[i][1] + bofs[1], 0.f);
        v0.z = fmaxf(acc[i][2] + bofs[2], 0.f);
        v0.w = fmaxf(acc[i][3] + bofs[3], 0.f);
        v1.x = fmaxf(acc[i][4] + bofs[4], 0.f);
        v1.y = fmaxf(acc[i][5] + bofs[5], 0.f);
        v1.z = fmaxf(acc[i][6] + bofs[6], 0.f);
        v1.w = fmaxf(acc[i][7] + bofs[7], 0.f);
        *(float4*)&C[(size_t)m * K_DIM + n0 + tx * 8] = v0;
        *(float4*)&C[(size_t)m * K_DIM + n0 + tx * 8 + 4] = v1;
    }
}

// ---------------- head: per-t gathered GEMM + relu + dot(Wh2) reduce ----------------
// Block: 64 gathered rows x 128 cols, full K=512, 256 threads, 4x8 per thread.
// out[b] += sum_n relu(l2[b]@Wh1[t] + bh1[t])[n] * Wh2[t][n]   (bh2 pre-added in k_pack)
__global__ void __launch_bounds__(256) k_head(
    const float* __restrict__ lat2,
    const float* __restrict__ Wh1, const float* __restrict__ bh1,
    const float* __restrict__ Wh2, float* __restrict__ out) {
    int t = blockIdx.z;
    int cnt = g_cnt[t];
    int tile = blockIdx.x;
    if (tile * 64 >= cnt) return;
    int n0 = blockIdx.y * 128;
    const float* W = Wh1 + (size_t)t * K_DIM * K_DIM;

    __shared__ int rows[64];
    __shared__ float As[2][8][64];
    __shared__ float Bs[2][8][128];
    __shared__ float red[64][17];

    int tid = threadIdx.x;
    if (tid < 64) {
        int idx = tile * 64 + tid;
        rows[tid] = g_bins[t * B_DIM + (idx < cnt ? idx : tile * 64)];
    }
    __syncthreads();

    int arow = tid >> 2;            // 0..63
    int acol = (tid & 3) * 2;       // 0,2,4,6
    int brow = tid >> 5;            // 0..7
    int bcol = (tid & 31) * 4;      // 0..124

    const float* Aptr = lat2 + (size_t)rows[arow] * K_DIM + acol;
    const float* Wp = W + (size_t)brow * K_DIM + n0 + bcol;

    int ty = tid >> 4;              // rows ty*4..ty*4+3
    int tx = tid & 15;              // cols tx*8..tx*8+7

    float acc[4][8];
#pragma unroll
    for (int i = 0; i < 4; i++)
#pragma unroll
        for (int j = 0; j < 8; j++) acc[i][j] = 0.f;

    float2 av = *(const float2*)(Aptr);
    float4 bv = *(const float4*)(Wp);
    As[0][acol + 0][arow] = av.x;
    As[0][acol + 1][arow] = av.y;
    *(float4*)&Bs[0][brow][bcol] = bv;
    __syncthreads();

    int buf = 0;
#pragma unroll 1
    for (int k0 = 0; k0 < K_DIM; k0 += 8) {
        bool last = (k0 + 8 >= K_DIM);
        if (!last) {
            av = *(const float2*)(Aptr + k0 + 8);
            bv = *(const float4*)(Wp + (size_t)(k0 + 8) * K_DIM);
        }
#pragma unroll
        for (int kk = 0; kk < 8; kk++) {
            float ra[4], rb[8];
#pragma unroll
            for (int i = 0; i < 4; i++) ra[i] = As[buf][kk][ty * 4 + i];
#pragma unroll
            for (int j = 0; j < 8; j++) rb[j] = Bs[buf][kk][tx * 8 + j];
#pragma unroll
            for (int i = 0; i < 4; i++)
#pragma unroll
                for (int j = 0; j < 8; j++) acc[i][j] += ra[i] * rb[j];
        }
        if (!last) {
            int nb = buf ^ 1;
            As[nb][acol + 0][arow] = av.x;
            As[nb][acol + 1][arow] = av.y;
            *(float4*)&Bs[nb][brow][bcol] = bv;
            __syncthreads();
            buf = nb;
        }
    }

    // fused epilogue: relu + weighted column sum
    float pb[4] = {0.f, 0.f, 0.f, 0.f};
#pragma unroll
    for (int j = 0; j < 8; j++) {
        int n = n0 + tx * 8 + j;
        float b1v = bh1[t * K_DIM + n];
        float w2v = Wh2[t * K_DIM + n];
#pragma unroll
        for (int i = 0; i < 4; i++) {
            float y = acc[i][j] + b1v;
            pb[i] += fmaxf(y, 0.f) * w2v;
        }
    }
#pragma unroll
    for (int i = 0; i < 4; i++) red[ty * 4 + i][tx] = pb[i];
    __syncthreads();
    if (tid < 64) {
        int idx = tile * 64 + tid;
        if (idx < cnt) {
            float s = 0.f;
#pragma unroll
            for (int x = 0; x < 16; x++) s += red[tid][x];
            atomicAdd(&out[rows[tid]], s);
        }
    }
}

// ---------------- launch ----------------
extern "C" void kernel_launch(void* const* d_in, const int* in_sizes, int n_in,
                              void* d_out, int out_size) {
    const float* in  = (const float*)d_in[0];
    const float* W1  = (const float*)d_in[1];
    const float* b1  = (const float*)d_in[2];
    const float* W2  = (const float*)d_in[3];
    const float* b2  = (const float*)d_in[4];
    const float* Wh1 = (const float*)d_in[5];
    const float* bh1 = (const float*)d_in[6];
    const float* Wh2 = (const float*)d_in[7];
    const float* bh2 = (const float*)d_in[8];
    float* out = (float*)d_out;

    float *px, *pl1, *pl2;
    cudaGetSymbolAddress((void**)&px, g_x);
    cudaGetSymbolAddress((void**)&pl1, g_lat1);
    cudaGetSymbolAddress((void**)&pl2, g_lat2);

    k_zero<<<1, 32>>>();
    k_pack<<<B_DIM / 8, 256>>>(in, bh2, out);
    k_gemm_relu<<<dim3(B_DIM / 128, K_DIM / 128), 256>>>(px, W1, b1, pl1);
    k_gemm_relu<<<dim3(B_DIM / 128, K_DIM / 128), 256>>>(pl1, W2, b2, pl2);
    // worst-case tiles per head = ceil(B/64) = 256; inactive blocks exit instantly
    k_head<<<dim3(256, K_DIM / 128, T_DIM), 256>>>(pl2, Wh1, bh1, Wh2, out);
}

// round 3
// speedup vs baseline: 2.5305x; 2.5305x over previous
#include <cuda_runtime.h>
#include <cuda_bf16.h>
#include <cstdint>

#define B_DIM 16384
#define K_DIM 512
#define T_DIM 16
#define IN_STRIDE 513
#define DSMEM_BYTES (65536 + 128)

// ---------------- device scratch ----------------
__device__ __nv_bfloat16 g_xhi[B_DIM * K_DIM], g_xlo[B_DIM * K_DIM];
__device__ __nv_bfloat16 g_l1hi[B_DIM * K_DIM], g_l1lo[B_DIM * K_DIM];
__device__ __nv_bfloat16 g_l2hi[B_DIM * K_DIM], g_l2lo[B_DIM * K_DIM];
__device__ __nv_bfloat16 g_w1hi[K_DIM * K_DIM], g_w1lo[K_DIM * K_DIM];
__device__ __nv_bfloat16 g_w2hi[K_DIM * K_DIM], g_w2lo[K_DIM * K_DIM];
__device__ __nv_bfloat16 g_whhi[T_DIM * K_DIM * K_DIM], g_whlo[T_DIM * K_DIM * K_DIM];
__device__ int g_bins[T_DIM * B_DIM];
__device__ int g_cnt[T_DIM];

// ---------------- PTX helpers (all sm_80-compatible) ----------------
__device__ __forceinline__ uint32_t smem_u32(const void* p) {
    uint32_t a;
    asm("{ .reg .u64 t; cvta.to.shared.u64 t, %1; cvt.u32.u64 %0, t; }" : "=r"(a) : "l"(p));
    return a;
}
__device__ __forceinline__ void cp16(uint32_t dst, const void* src) {
    asm volatile("cp.async.cg.shared.global [%0], [%1], 16;" :: "r"(dst), "l"(src));
}
__device__ __forceinline__ void cp_commit() { asm volatile("cp.async.commit_group;"); }
template <int N>
__device__ __forceinline__ void cp_wait() { asm volatile("cp.async.wait_group %0;" :: "n"(N)); }

__device__ __forceinline__ void ldsm4(uint32_t addr, uint32_t& r0, uint32_t& r1,
                                      uint32_t& r2, uint32_t& r3) {
    asm volatile("ldmatrix.sync.aligned.m8n8.x4.shared.b16 {%0,%1,%2,%3}, [%4];"
                 : "=r"(r0), "=r"(r1), "=r"(r2), "=r"(r3) : "r"(addr));
}
__device__ __forceinline__ void mma16816(float* c, uint32_t a0, uint32_t a1, uint32_t a2,
                                         uint32_t a3, uint32_t b0, uint32_t b1) {
    asm volatile(
        "mma.sync.aligned.m16n8k16.row.col.f32.bf16.bf16.f32 "
        "{%0,%1,%2,%3}, {%4,%5,%6,%7}, {%8,%9}, {%0,%1,%2,%3};"
        : "+f"(c[0]), "+f"(c[1]), "+f"(c[2]), "+f"(c[3])
        : "r"(a0), "r"(a1), "r"(a2), "r"(a3), "r"(b0), "r"(b1));
}

// XOR swizzle on 16B chunks: row stride 64B, conflict-minimal for ldmatrix
__device__ __forceinline__ uint32_t swz(uint32_t base, uint32_t row, uint32_t ch) {
    return base + row * 64u + ((ch ^ ((row >> 1) & 3u)) << 4);
}

// ---------------- small prep kernels ----------------
__global__ void k_zero() {
    if (threadIdx.x < T_DIM) g_cnt[threadIdx.x] = 0;
}

__global__ void k_prep(const float* __restrict__ in, const float* __restrict__ bh2,
                       float* __restrict__ out) {
    int base = blockIdx.x * 8;
    for (int i = threadIdx.x; i < 8 * K_DIM; i += 256) {
        int r = i >> 9, c = i & 511;
        float v = in[(size_t)(base + r) * IN_STRIDE + c];
        __nv_bfloat16 h = __float2bfloat16(v);
        size_t o = (size_t)(base + r) * K_DIM + c;
        g_xhi[o] = h;
        g_xlo[o] = __float2bfloat16(v - __bfloat162float(h));
    }
    if (threadIdx.x < 8) {
        int b = base + threadIdx.x;
        int t = (int)in[(size_t)b * IN_STRIDE + K_DIM];
        int pos = atomicAdd(&g_cnt[t], 1);
        g_bins[t * B_DIM + pos] = b;
        out[b] = bh2[t];
    }
}

// transpose [K,N] fp32 -> [N,K] bf16 hi/lo
__global__ void k_convw(const float* __restrict__ W,
                        __nv_bfloat16* __restrict__ hi, __nv_bfloat16* __restrict__ lo) {
    __shared__ float tile[32][33];
    int mat = blockIdx.z;
    const float* Wm = W + (size_t)mat * K_DIM * K_DIM;
    int k0 = blockIdx.x * 32, n0 = blockIdx.y * 32;
    for (int ky = threadIdx.y; ky < 32; ky += 8)
        tile[ky][threadIdx.x] = Wm[(size_t)(k0 + ky) * K_DIM + n0 + threadIdx.x];
    __syncthreads();
    for (int ny = threadIdx.y; ny < 32; ny += 8) {
        float v = tile[threadIdx.x][ny];
        __nv_bfloat16 h = __float2bfloat16(v);
        size_t o = (size_t)mat * K_DIM * K_DIM + (size_t)(n0 + ny) * K_DIM + k0 + threadIdx.x;
        hi[o] = h;
        lo[o] = __float2bfloat16(v - __bfloat162float(h));
    }
}

// ---------------- tile loads: 4 sub-tiles (Ahi,Alo,Bhi,Blo), each 128x32 bf16 ----------------
__device__ __forceinline__ void issue_chunk(
    uint32_t sbuf, int stage, int k0, const int* __restrict__ rows_s, int bn0,
    const __nv_bfloat16* __restrict__ Ahi, const __nv_bfloat16* __restrict__ Alo,
    const __nv_bfloat16* __restrict__ Bhi, const __nv_bfloat16* __restrict__ Blo, int tid) {
    uint32_t sb = sbuf + (uint32_t)stage * 32768u;
#pragma unroll
    for (int i = 0; i < 8; i++) {
        int idx = tid + i * 256;
        int tile = idx >> 9, w = idx & 511, row = w >> 2, ch = w & 3;
        const __nv_bfloat16* src;
        int gr;
        if (tile == 0)      { src = Ahi; gr = rows_s[row]; }
        else if (tile == 1) { src = Alo; gr = rows_s[row]; }
        else if (tile == 2) { src = Bhi; gr = bn0 + row; }
        else                { src = Blo; gr = bn0 + row; }
        cp16(swz(sb + (uint32_t)tile * 8192u, (uint32_t)row, (uint32_t)ch),
             src + (size_t)gr * K_DIM + k0 + ch * 8);
    }
    cp_commit();
}

// ---------------- per-chunk MMA: 3 passes (hi*hi, lo*hi, hi*lo) ----------------
__device__ __forceinline__ void compute_chunk(float acc[4][4][4], uint32_t sbuf, int stage,
                                              int lane, int wm, int wn) {
    uint32_t sb = sbuf + (uint32_t)stage * 32768u;
    uint32_t A_hi = sb, A_lo = sb + 8192u, B_hi = sb + 16384u, B_lo = sb + 24576u;
    uint32_t lrow = (uint32_t)(lane & 15);
    uint32_t lsel = (uint32_t)(lane >> 4);
#pragma unroll
    for (int kk = 0; kk < 2; kk++) {
        uint32_t ch = (uint32_t)(kk * 2) + lsel;
        uint32_t ah[4][4], bb[2][4], b2[2][4];
#pragma unroll
        for (int im = 0; im < 4; im++)
            ldsm4(swz(A_hi, (uint32_t)(wm * 64 + im * 16) + lrow, ch),
                  ah[im][0], ah[im][1], ah[im][2], ah[im][3]);
#pragma unroll
        for (int jn = 0; jn < 2; jn++)
            ldsm4(swz(B_hi, (uint32_t)(wn * 32 + jn * 16) + lrow, ch),
                  bb[jn][0], bb[jn][1], bb[jn][2], bb[jn][3]);
        // pass 0: hi*hi
#pragma unroll
        for (int im = 0; im < 4; im++)
#pragma unroll
            for (int j = 0; j < 4; j++)
                mma16816(acc[im][j], ah[im][0], ah[im][1], ah[im][2], ah[im][3],
                         bb[j >> 1][j & 1], bb[j >> 1][(j & 1) + 2]);
        // pass 1: hi*lo (load Blo into b2)
#pragma unroll
        for (int jn = 0; jn < 2; jn++)
            ldsm4(swz(B_lo, (uint32_t)(wn * 32 + jn * 16) + lrow, ch),
                  b2[jn][0], b2[jn][1], b2[jn][2], b2[jn][3]);
#pragma unroll
        for (int im = 0; im < 4; im++)
#pragma unroll
            for (int j = 0; j < 4; j++)
                mma16816(acc[im][j], ah[im][0], ah[im][1], ah[im][2], ah[im][3],
                         b2[j >> 1][j & 1], b2[j >> 1][(j & 1) + 2]);
        // pass 2: lo*hi (reload A as lo, reuse bb = Bhi)
#pragma unroll
        for (int im = 0; im < 4; im++)
            ldsm4(swz(A_lo, (uint32_t)(wm * 64 + im * 16) + lrow, ch),
                  ah[im][0], ah[im][1], ah[im][2], ah[im][3]);
#pragma unroll
        for (int im = 0; im < 4; im++)
#pragma unroll
            for (int j = 0; j < 4; j++)
                mma16816(acc[im][j], ah[im][0], ah[im][1], ah[im][2], ah[im][3],
                         bb[j >> 1][j & 1], bb[j >> 1][(j & 1) + 2]);
    }
}

__device__ __forceinline__ void mma_mainloop(
    float acc[4][4][4], uint32_t sbuf, const int* __restrict__ rows_s, int bn0,
    const __nv_bfloat16* __restrict__ Ahi, const __nv_bfloat16* __restrict__ Alo,
    const __nv_bfloat16* __restrict__ Bhi, const __nv_bfloat16* __restrict__ Blo,
    int tid, int lane, int wm, int wn) {
    issue_chunk(sbuf, 0, 0, rows_s, bn0, Ahi, Alo, Bhi, Blo, tid);
#pragma unroll 1
    for (int c = 0; c < 16; c++) {
        if (c < 15) {
            issue_chunk(sbuf, (c + 1) & 1, (c + 1) * 32, rows_s, bn0, Ahi, Alo, Bhi, Blo, tid);
            cp_wait<1>();
        } else {
            cp_wait<0>();
        }
        __syncthreads();
        compute_chunk(acc, sbuf, c & 1, lane, wm, wn);
        __syncthreads();
    }
}

// ---------------- GEMM + bias + relu -> bf16 hi/lo ----------------
__global__ void __launch_bounds__(256) k_mm(
    const __nv_bfloat16* __restrict__ Ahi, const __nv_bfloat16* __restrict__ Alo,
    const __nv_bfloat16* __restrict__ Bhi, const __nv_bfloat16* __restrict__ Blo,
    const float* __restrict__ bias,
    __nv_bfloat16* __restrict__ Chi, __nv_bfloat16* __restrict__ Clo) {
    extern __shared__ char dsmem[];
    __shared__ int rows_s[128];
    __shared__ float sbias[128];
    uint32_t sbuf = (smem_u32(dsmem) + 127u) & ~127u;

    int tid = threadIdx.x, lane = tid & 31, wid = tid >> 5;
    int wm = wid & 1, wn = wid >> 1;
    int m0 = blockIdx.x * 128, n0 = blockIdx.y * 128;

    if (tid < 128) { rows_s[tid] = m0 + tid; sbias[tid] = bias[n0 + tid]; }
    __syncthreads();

    float acc[4][4][4];
#pragma unroll
    for (int a = 0; a < 4; a++)
#pragma unroll
        for (int b = 0; b < 4; b++)
#pragma unroll
            for (int d = 0; d < 4; d++) acc[a][b][d] = 0.f;

    mma_mainloop(acc, sbuf, rows_s, n0, Ahi, Alo, Bhi, Blo, tid, lane, wm, wn);

    // epilogue: bias + relu -> split bf16 hi/lo, store
#pragma unroll
    for (int im = 0; im < 4; im++) {
        int r0 = m0 + wm * 64 + im * 16 + (lane >> 2);
#pragma unroll
        for (int j = 0; j < 4; j++) {
            int nloc = wn * 32 + j * 8 + (lane & 3) * 2;
            float v0 = fmaxf(acc[im][j][0] + sbias[nloc],     0.f);
            float v1 = fmaxf(acc[im][j][1] + sbias[nloc + 1], 0.f);
            float v2 = fmaxf(acc[im][j][2] + sbias[nloc],     0.f);
            float v3 = fmaxf(acc[im][j][3] + sbias[nloc + 1], 0.f);
            __nv_bfloat16 h0 = __float2bfloat16(v0), h1 = __float2bfloat16(v1);
            __nv_bfloat16 h2 = __float2bfloat16(v2), h3 = __float2bfloat16(v3);
            __nv_bfloat16 l0 = __float2bfloat16(v0 - __bfloat162float(h0));
            __nv_bfloat16 l1 = __float2bfloat16(v1 - __bfloat162float(h1));
            __nv_bfloat16 l2 = __float2bfloat16(v2 - __bfloat162float(h2));
            __nv_bfloat16 l3 = __float2bfloat16(v3 - __bfloat162float(h3));
            size_t o0 = (size_t)r0 * K_DIM + n0 + nloc;
            size_t o1 = (size_t)(r0 + 8) * K_DIM + n0 + nloc;
            *(uint32_t*)(Chi + o0) = (uint32_t)__bfloat16_as_ushort(h0) | ((uint32_t)__bfloat16_as_ushort(h1) << 16);
            *(uint32_t*)(Chi + o1) = (uint32_t)__bfloat16_as_ushort(h2) | ((uint32_t)__bfloat16_as_ushort(h3) << 16);
            *(uint32_t*)(Clo + o0) = (uint32_t)__bfloat16_as_ushort(l0) | ((uint32_t)__bfloat16_as_ushort(l1) << 16);
            *(uint32_t*)(Clo + o1) = (uint32_t)__bfloat16_as_ushort(l2) | ((uint32_t)__bfloat16_as_ushort(l3) << 16);
        }
    }
}

// ---------------- head: gathered GEMM + relu + dot(Wh2) reduce ----------------
__global__ void __launch_bounds__(256) k_head(
    const __nv_bfloat16* __restrict__ l2hi, const __nv_bfloat16* __restrict__ l2lo,
    const __nv_bfloat16* __restrict__ whhi, const __nv_bfloat16* __restrict__ whlo,
    const float* __restrict__ bh1, const float* __restrict__ Wh2,
    float* __restrict__ out) {
    int t = blockIdx.z;
    int cnt = g_cnt[t];
    int tile = blockIdx.x;
    if (tile * 128 >= cnt) return;
    int n0 = blockIdx.y * 128;

    extern __shared__ char dsmem[];
    __shared__ int rows_s[128];
    __shared__ float sbh1[128];
    __shared__ float swh2[128];
    uint32_t sbuf = (smem_u32(dsmem) + 127u) & ~127u;

    int tid = threadIdx.x, lane = tid & 31, wid = tid >> 5;
    int wm = wid & 1, wn = wid >> 1;

    if (tid < 128) {
        int idx = tile * 128 + tid;
        rows_s[tid] = g_bins[t * B_DIM + (idx < cnt ? idx : cnt - 1)];
        sbh1[tid] = bh1[t * K_DIM + n0 + tid];
        swh2[tid] = Wh2[t * K_DIM + n0 + tid];
    }
    __syncthreads();

    float acc[4][4][4];
#pragma unroll
    for (int a = 0; a < 4; a++)
#pragma unroll
        for (int b = 0; b < 4; b++)
#pragma unroll
            for (int d = 0; d < 4; d++) acc[a][b][d] = 0.f;

    mma_mainloop(acc, sbuf, rows_s, n0,
                 l2hi, l2lo,
                 whhi + (size_t)t * K_DIM * K_DIM, whlo + (size_t)t * K_DIM * K_DIM,
                 tid, lane, wm, wn);

    // epilogue: relu + dot with Wh2, reduce across the 4 lanes sharing a row
#pragma unroll
    for (int im = 0; im < 4; im++) {
        float p0 = 0.f, p1 = 0.f;
#pragma unroll
        for (int j = 0; j < 4; j++) {
            int nloc = wn * 32 + j * 8 + (lane & 3) * 2;
            float w0 = swh2[nloc], w1 = swh2[nloc + 1];
            float q0 = sbh1[nloc], q1 = sbh1[nloc + 1];
            p0 = fmaf(fmaxf(acc[im][j][0] + q0, 0.f), w0, p0);
            p0 = fmaf(fmaxf(acc[im][j][1] + q1, 0.f), w1, p0);
            p1 = fmaf(fmaxf(acc[im][j][2] + q0, 0.f), w0, p1);
            p1 = fmaf(fmaxf(acc[im][j][3] + q1, 0.f), w1, p1);
        }
        p0 += __shfl_xor_sync(0xffffffffu, p0, 1);
        p0 += __shfl_xor_sync(0xffffffffu, p0, 2);
        p1 += __shfl_xor_sync(0xffffffffu, p1, 1);
        p1 += __shfl_xor_sync(0xffffffffu, p1, 2);
        if ((lane & 3) == 0) {
            int rl0 = wm * 64 + im * 16 + (lane >> 2);
            int rl1 = rl0 + 8;
            if (tile * 128 + rl0 < cnt) atomicAdd(&out[rows_s[rl0]], p0);
            if (tile * 128 + rl1 < cnt) atomicAdd(&out[rows_s[rl1]], p1);
        }
    }
}

// ---------------- launch ----------------
extern "C" void kernel_launch(void* const* d_in, const int* in_sizes, int n_in,
                              void* d_out, int out_size) {
    const float* in  = (const float*)d_in[0];
    const float* W1  = (const float*)d_in[1];
    const float* b1  = (const float*)d_in[2];
    const float* W2  = (const float*)d_in[3];
    const float* b2  = (const float*)d_in[4];
    const float* Wh1 = (const float*)d_in[5];
    const float* bh1 = (const float*)d_in[6];
    const float* Wh2 = (const float*)d_in[7];
    const float* bh2 = (const float*)d_in[8];
    float* out = (float*)d_out;

    cudaFuncSetAttribute(k_mm,   cudaFuncAttributeMaxDynamicSharedMemorySize, DSMEM_BYTES);
    cudaFuncSetAttribute(k_head, cudaFuncAttributeMaxDynamicSharedMemorySize, DSMEM_BYTES);

    __nv_bfloat16 *xhi, *xlo, *l1hi, *l1lo, *l2hi, *l2lo;
    __nv_bfloat16 *w1hi, *w1lo, *w2hi, *w2lo, *whhi, *whlo;
    cudaGetSymbolAddress((void**)&xhi,  g_xhi);  cudaGetSymbolAddress((void**)&xlo,  g_xlo);
    cudaGetSymbolAddress((void**)&l1hi, g_l1hi); cudaGetSymbolAddress((void**)&l1lo, g_l1lo);
    cudaGetSymbolAddress((void**)&l2hi, g_l2hi); cudaGetSymbolAddress((void**)&l2lo, g_l2lo);
    cudaGetSymbolAddress((void**)&w1hi, g_w1hi); cudaGetSymbolAddress((void**)&w1lo, g_w1lo);
    cudaGetSymbolAddress((void**)&w2hi, g_w2hi); cudaGetSymbolAddress((void**)&w2lo, g_w2lo);
    cudaGetSymbolAddress((void**)&whhi, g_whhi); cudaGetSymbolAddress((void**)&whlo, g_whlo);

    k_zero<<<1, 32>>>();
    k_prep<<<B_DIM / 8, 256>>>(in, bh2, out);
    k_convw<<<dim3(16, 16, 1),  dim3(32, 8)>>>(W1,  w1hi, w1lo);
    k_convw<<<dim3(16, 16, 1),  dim3(32, 8)>>>(W2,  w2hi, w2lo);
    k_convw<<<dim3(16, 16, 16), dim3(32, 8)>>>(Wh1, whhi, whlo);
    k_mm<<<dim3(B_DIM / 128, 4), 256, DSMEM_BYTES>>>(xhi, xlo, w1hi, w1lo, b1, l1hi, l1lo);
    k_mm<<<dim3(B_DIM / 128, 4), 256, DSMEM_BYTES>>>(l1hi, l1lo, w2hi, w2lo, b2, l2hi, l2lo);
    k_head<<<dim3(128, 4, 16), 256, DSMEM_BYTES>>>(l2hi, l2lo, whhi, whlo, bh1, Wh2, out);
}

// round 4
// speedup vs baseline: 2.5672x; 1.0145x over previous
#include <cuda_runtime.h>
#include <cuda_bf16.h>
#include <cstdint>

#define B_DIM 16384
#define K_DIM 512
#define T_DIM 16
#define IN_STRIDE 513
#define DSMEM_BYTES (3 * 32768 + 128)

// ---------------- device scratch ----------------
__device__ __nv_bfloat16 g_xhi[B_DIM * K_DIM], g_xlo[B_DIM * K_DIM];
__device__ __nv_bfloat16 g_l1hi[B_DIM * K_DIM], g_l1lo[B_DIM * K_DIM];
__device__ __nv_bfloat16 g_l2hi[B_DIM * K_DIM], g_l2lo[B_DIM * K_DIM];
__device__ __nv_bfloat16 g_w1hi[K_DIM * K_DIM], g_w1lo[K_DIM * K_DIM];
__device__ __nv_bfloat16 g_w2hi[K_DIM * K_DIM], g_w2lo[K_DIM * K_DIM];
__device__ __nv_bfloat16 g_whhi[T_DIM * K_DIM * K_DIM], g_whlo[T_DIM * K_DIM * K_DIM];
__device__ int g_bins[T_DIM * B_DIM];
__device__ int g_cnt[T_DIM];

// ---------------- PTX helpers (sm_80-compatible) ----------------
__device__ __forceinline__ uint32_t smem_u32(const void* p) {
    uint32_t a;
    asm("{ .reg .u64 t; cvta.to.shared.u64 t, %1; cvt.u32.u64 %0, t; }" : "=r"(a) : "l"(p));
    return a;
}
__device__ __forceinline__ void cp16(uint32_t dst, const void* src) {
    asm volatile("cp.async.cg.shared.global [%0], [%1], 16;" :: "r"(dst), "l"(src));
}
__device__ __forceinline__ void cp_commit() { asm volatile("cp.async.commit_group;"); }
template <int N>
__device__ __forceinline__ void cp_wait() { asm volatile("cp.async.wait_group %0;" :: "n"(N)); }

__device__ __forceinline__ void ldsm4(uint32_t addr, uint32_t& r0, uint32_t& r1,
                                      uint32_t& r2, uint32_t& r3) {
    asm volatile("ldmatrix.sync.aligned.m8n8.x4.shared.b16 {%0,%1,%2,%3}, [%4];"
                 : "=r"(r0), "=r"(r1), "=r"(r2), "=r"(r3) : "r"(addr));
}
__device__ __forceinline__ void mma16816(float* c, uint32_t a0, uint32_t a1, uint32_t a2,
                                         uint32_t a3, uint32_t b0, uint32_t b1) {
    asm volatile(
        "mma.sync.aligned.m16n8k16.row.col.f32.bf16.bf16.f32 "
        "{%0,%1,%2,%3}, {%4,%5,%6,%7}, {%8,%9}, {%0,%1,%2,%3};"
        : "+f"(c[0]), "+f"(c[1]), "+f"(c[2]), "+f"(c[3])
        : "r"(a0), "r"(a1), "r"(a2), "r"(a3), "r"(b0), "r"(b1));
}

// XOR swizzle on 16B chunks: row stride 64B
__device__ __forceinline__ uint32_t swz(uint32_t base, uint32_t row, uint32_t ch) {
    return base + row * 64u + ((ch ^ ((row >> 1) & 3u)) << 4);
}

// ---------------- small prep kernels ----------------
__global__ void k_zero() {
    if (threadIdx.x < T_DIM) g_cnt[threadIdx.x] = 0;
}

__global__ void k_prep(const float* __restrict__ in, const float* __restrict__ bh2,
                       float* __restrict__ out) {
    int base = blockIdx.x * 8;
    for (int i = threadIdx.x; i < 8 * K_DIM; i += 256) {
        int r = i >> 9, c = i & 511;
        float v = in[(size_t)(base + r) * IN_STRIDE + c];
        __nv_bfloat16 h = __float2bfloat16(v);
        size_t o = (size_t)(base + r) * K_DIM + c;
        g_xhi[o] = h;
        g_xlo[o] = __float2bfloat16(v - __bfloat162float(h));
    }
    if (threadIdx.x < 8) {
        int b = base + threadIdx.x;
        int t = (int)in[(size_t)b * IN_STRIDE + K_DIM];
        int pos = atomicAdd(&g_cnt[t], 1);
        g_bins[t * B_DIM + pos] = b;
        out[b] = bh2[t];
    }
}

// merged transpose+split of ALL weight matrices: z=0 -> W1, z=1 -> W2, z>=2 -> Wh1[z-2]
__global__ void k_convw(const float* __restrict__ W1, const float* __restrict__ W2,
                        const float* __restrict__ Wh1) {
    __shared__ float tile[32][33];
    int z = blockIdx.z;
    const float* Wm;
    __nv_bfloat16 *hi, *lo;
    size_t obase;
    if (z == 0)      { Wm = W1; hi = g_w1hi; lo = g_w1lo; obase = 0; }
    else if (z == 1) { Wm = W2; hi = g_w2hi; lo = g_w2lo; obase = 0; }
    else {
        int mat = z - 2;
        Wm = Wh1 + (size_t)mat * K_DIM * K_DIM;
        hi = g_whhi; lo = g_whlo;
        obase = (size_t)mat * K_DIM * K_DIM;
    }
    int k0 = blockIdx.x * 32, n0 = blockIdx.y * 32;
    for (int ky = threadIdx.y; ky < 32; ky += 8)
        tile[ky][threadIdx.x] = Wm[(size_t)(k0 + ky) * K_DIM + n0 + threadIdx.x];
    __syncthreads();
    for (int ny = threadIdx.y; ny < 32; ny += 8) {
        float v = tile[threadIdx.x][ny];
        __nv_bfloat16 h = __float2bfloat16(v);
        size_t o = obase + (size_t)(n0 + ny) * K_DIM + k0 + threadIdx.x;
        hi[o] = h;
        lo[o] = __float2bfloat16(v - __bfloat162float(h));
    }
}

// ---------------- tile loads: 4 sub-tiles (Ahi,Alo,Bhi,Blo), each 128x32 bf16 ----------------
__device__ __forceinline__ void issue_chunk(
    uint32_t sbuf, int stage, int k0, const int* __restrict__ rows_s, int bn0,
    const __nv_bfloat16* __restrict__ Ahi, const __nv_bfloat16* __restrict__ Alo,
    const __nv_bfloat16* __restrict__ Bhi, const __nv_bfloat16* __restrict__ Blo, int tid) {
    uint32_t sb = sbuf + (uint32_t)stage * 32768u;
#pragma unroll
    for (int i = 0; i < 8; i++) {
        int idx = tid + i * 256;
        int tile = idx >> 9, w = idx & 511, row = w >> 2, ch = w & 3;
        const __nv_bfloat16* src;
        int gr;
        if (tile == 0)      { src = Ahi; gr = rows_s[row]; }
        else if (tile == 1) { src = Alo; gr = rows_s[row]; }
        else if (tile == 2) { src = Bhi; gr = bn0 + row; }
        else                { src = Blo; gr = bn0 + row; }
        cp16(swz(sb + (uint32_t)tile * 8192u, (uint32_t)row, (uint32_t)ch),
             src + (size_t)gr * K_DIM + k0 + ch * 8);
    }
    cp_commit();
}

// ---------------- per-chunk MMA: 3 passes (hi*hi, hi*lo, lo*hi) ----------------
__device__ __forceinline__ void compute_chunk(float acc[4][4][4], uint32_t sbuf, int stage,
                                              int lane, int wm, int wn) {
    uint32_t sb = sbuf + (uint32_t)stage * 32768u;
    uint32_t A_hi = sb, A_lo = sb + 8192u, B_hi = sb + 16384u, B_lo = sb + 24576u;
    uint32_t lrow = (uint32_t)(lane & 15);
    uint32_t lsel = (uint32_t)(lane >> 4);
#pragma unroll
    for (int kk = 0; kk < 2; kk++) {
        uint32_t ch = (uint32_t)(kk * 2) + lsel;
        uint32_t ah[4][4], bb[2][4], b2[2][4];
#pragma unroll
        for (int im = 0; im < 4; im++)
            ldsm4(swz(A_hi, (uint32_t)(wm * 64 + im * 16) + lrow, ch),
                  ah[im][0], ah[im][1], ah[im][2], ah[im][3]);
#pragma unroll
        for (int jn = 0; jn < 2; jn++)
            ldsm4(swz(B_hi, (uint32_t)(wn * 32 + jn * 16) + lrow, ch),
                  bb[jn][0], bb[jn][1], bb[jn][2], bb[jn][3]);
#pragma unroll
        for (int im = 0; im < 4; im++)
#pragma unroll
            for (int j = 0; j < 4; j++)
                mma16816(acc[im][j], ah[im][0], ah[im][1], ah[im][2], ah[im][3],
                         bb[j >> 1][j & 1], bb[j >> 1][(j & 1) + 2]);
#pragma unroll
        for (int jn = 0; jn < 2; jn++)
            ldsm4(swz(B_lo, (uint32_t)(wn * 32 + jn * 16) + lrow, ch),
                  b2[jn][0], b2[jn][1], b2[jn][2], b2[jn][3]);
#pragma unroll
        for (int im = 0; im < 4; im++)
#pragma unroll
            for (int j = 0; j < 4; j++)
                mma16816(acc[im][j], ah[im][0], ah[im][1], ah[im][2], ah[im][3],
                         b2[j >> 1][j & 1], b2[j >> 1][(j & 1) + 2]);
#pragma unroll
        for (int im = 0; im < 4; im++)
            ldsm4(swz(A_lo, (uint32_t)(wm * 64 + im * 16) + lrow, ch),
                  ah[im][0], ah[im][1], ah[im][2], ah[im][3]);
#pragma unroll
        for (int im = 0; im < 4; im++)
#pragma unroll
            for (int j = 0; j < 4; j++)
                mma16816(acc[im][j], ah[im][0], ah[im][1], ah[im][2], ah[im][3],
                         bb[j >> 1][j & 1], bb[j >> 1][(j & 1) + 2]);
    }
}

// 3-stage pipeline, ONE barrier per iteration.
__device__ __forceinline__ void mma_mainloop(
    float acc[4][4][4], uint32_t sbuf, const int* __restrict__ rows_s, int bn0,
    const __nv_bfloat16* __restrict__ Ahi, const __nv_bfloat16* __restrict__ Alo,
    const __nv_bfloat16* __restrict__ Bhi, const __nv_bfloat16* __restrict__ Blo,
    int tid, int lane, int wm, int wn) {
    issue_chunk(sbuf, 0, 0, rows_s, bn0, Ahi, Alo, Bhi, Blo, tid);
    issue_chunk(sbuf, 1, 32, rows_s, bn0, Ahi, Alo, Bhi, Blo, tid);
    int stage = 0;
#pragma unroll 1
    for (int c = 0; c < 16; c++) {
        if (c >= 14) cp_wait<0>(); else cp_wait<1>();
        __syncthreads();
        if (c + 2 < 16) {
            int ns = stage + 2; if (ns >= 3) ns -= 3;
            issue_chunk(sbuf, ns, (c + 2) * 32, rows_s, bn0, Ahi, Alo, Bhi, Blo, tid);
        }
        compute_chunk(acc, sbuf, stage, lane, wm, wn);
        if (++stage == 3) stage = 0;
    }
}

// ---------------- GEMM + bias + relu -> bf16 hi/lo ----------------
__global__ void __launch_bounds__(256) k_mm(
    const __nv_bfloat16* __restrict__ Ahi, const __nv_bfloat16* __restrict__ Alo,
    const __nv_bfloat16* __restrict__ Bhi, const __nv_bfloat16* __restrict__ Blo,
    const float* __restrict__ bias,
    __nv_bfloat16* __restrict__ Chi, __nv_bfloat16* __restrict__ Clo) {
    extern __shared__ char dsmem[];
    __shared__ int rows_s[128];
    __shared__ float sbias[128];
    uint32_t sbuf = (smem_u32(dsmem) + 127u) & ~127u;

    int tid = threadIdx.x, lane = tid & 31, wid = tid >> 5;
    int wm = wid & 1, wn = wid >> 1;
    int m0 = blockIdx.x * 128, n0 = blockIdx.y * 128;

    if (tid < 128) { rows_s[tid] = m0 + tid; sbias[tid] = bias[n0 + tid]; }
    __syncthreads();

    float acc[4][4][4];
#pragma unroll
    for (int a = 0; a < 4; a++)
#pragma unroll
        for (int b = 0; b < 4; b++)
#pragma unroll
            for (int d = 0; d < 4; d++) acc[a][b][d] = 0.f;

    mma_mainloop(acc, sbuf, rows_s, n0, Ahi, Alo, Bhi, Blo, tid, lane, wm, wn);

#pragma unroll
    for (int im = 0; im < 4; im++) {
        int r0 = m0 + wm * 64 + im * 16 + (lane >> 2);
#pragma unroll
        for (int j = 0; j < 4; j++) {
            int nloc = wn * 32 + j * 8 + (lane & 3) * 2;
            float v0 = fmaxf(acc[im][j][0] + sbias[nloc],     0.f);
            float v1 = fmaxf(acc[im][j][1] + sbias[nloc + 1], 0.f);
            float v2 = fmaxf(acc[im][j][2] + sbias[nloc],     0.f);
            float v3 = fmaxf(acc[im][j][3] + sbias[nloc + 1], 0.f);
            __nv_bfloat16 h0 = __float2bfloat16(v0), h1 = __float2bfloat16(v1);
            __nv_bfloat16 h2 = __float2bfloat16(v2), h3 = __float2bfloat16(v3);
            __nv_bfloat16 l0 = __float2bfloat16(v0 - __bfloat162float(h0));
            __nv_bfloat16 l1 = __float2bfloat16(v1 - __bfloat162float(h1));
            __nv_bfloat16 l2 = __float2bfloat16(v2 - __bfloat162float(h2));
            __nv_bfloat16 l3 = __float2bfloat16(v3 - __bfloat162float(h3));
            size_t o0 = (size_t)r0 * K_DIM + n0 + nloc;
            size_t o1 = (size_t)(r0 + 8) * K_DIM + n0 + nloc;
            *(uint32_t*)(Chi + o0) = (uint32_t)__bfloat16_as_ushort(h0) | ((uint32_t)__bfloat16_as_ushort(h1) << 16);
            *(uint32_t*)(Chi + o1) = (uint32_t)__bfloat16_as_ushort(h2) | ((uint32_t)__bfloat16_as_ushort(h3) << 16);
            *(uint32_t*)(Clo + o0) = (uint32_t)__bfloat16_as_ushort(l0) | ((uint32_t)__bfloat16_as_ushort(l1) << 16);
            *(uint32_t*)(Clo + o1) = (uint32_t)__bfloat16_as_ushort(l2) | ((uint32_t)__bfloat16_as_ushort(l3) << 16);
        }
    }
}

// ---------------- head: gathered GEMM + relu + dot(Wh2) reduce ----------------
__global__ void __launch_bounds__(256) k_head(
    const __nv_bfloat16* __restrict__ l2hi, const __nv_bfloat16* __restrict__ l2lo,
    const __nv_bfloat16* __restrict__ whhi, const __nv_bfloat16* __restrict__ whlo,
    const float* __restrict__ bh1, const float* __restrict__ Wh2,
    float* __restrict__ out) {
    int t = blockIdx.z;
    int cnt = g_cnt[t];
    int tile = blockIdx.x;
    if (tile * 128 >= cnt) return;
    int n0 = blockIdx.y * 128;

    extern __shared__ char dsmem[];
    __shared__ int rows_s[128];
    __shared__ float sbh1[128];
    __shared__ float swh2[128];
    uint32_t sbuf = (smem_u32(dsmem) + 127u) & ~127u;

    int tid = threadIdx.x, lane = tid & 31, wid = tid >> 5;
    int wm = wid & 1, wn = wid >> 1;

    if (tid < 128) {
        int idx = tile * 128 + tid;
        rows_s[tid] = g_bins[t * B_DIM + (idx < cnt ? idx : cnt - 1)];
        sbh1[tid] = bh1[t * K_DIM + n0 + tid];
        swh2[tid] = Wh2[t * K_DIM + n0 + tid];
    }
    __syncthreads();

    float acc[4][4][4];
#pragma unroll
    for (int a = 0; a < 4; a++)
#pragma unroll
        for (int b = 0; b < 4; b++)
#pragma unroll
            for (int d = 0; d < 4; d++) acc[a][b][d] = 0.f;

    mma_mainloop(acc, sbuf, rows_s, n0,
                 l2hi, l2lo,
                 whhi + (size_t)t * K_DIM * K_DIM, whlo + (size_t)t * K_DIM * K_DIM,
                 tid, lane, wm, wn);

#pragma unroll
    for (int im = 0; im < 4; im++) {
        float p0 = 0.f, p1 = 0.f;
#pragma unroll
        for (int j = 0; j < 4; j++) {
            int nloc = wn * 32 + j * 8 + (lane & 3) * 2;
            float w0 = swh2[nloc], w1 = swh2[nloc + 1];
            float q0 = sbh1[nloc], q1 = sbh1[nloc + 1];
            p0 = fmaf(fmaxf(acc[im][j][0] + q0, 0.f), w0, p0);
            p0 = fmaf(fmaxf(acc[im][j][1] + q1, 0.f), w1, p0);
            p1 = fmaf(fmaxf(acc[im][j][2] + q0, 0.f), w0, p1);
            p1 = fmaf(fmaxf(acc[im][j][3] + q1, 0.f), w1, p1);
        }
        p0 += __shfl_xor_sync(0xffffffffu, p0, 1);
        p0 += __shfl_xor_sync(0xffffffffu, p0, 2);
        p1 += __shfl_xor_sync(0xffffffffu, p1, 1);
        p1 += __shfl_xor_sync(0xffffffffu, p1, 2);
        if ((lane & 3) == 0) {
            int rl0 = wm * 64 + im * 16 + (lane >> 2);
            int rl1 = rl0 + 8;
            if (tile * 128 + rl0 < cnt) atomicAdd(&out[rows_s[rl0]], p0);
            if (tile * 128 + rl1 < cnt) atomicAdd(&out[rows_s[rl1]], p1);
        }
    }
}

// ---------------- launch ----------------
extern "C" void kernel_launch(void* const* d_in, const int* in_sizes, int n_in,
                              void* d_out, int out_size) {
    const float* in  = (const float*)d_in[0];
    const float* W1  = (const float*)d_in[1];
    const float* b1  = (const float*)d_in[2];
    const float* W2  = (const float*)d_in[3];
    const float* b2  = (const float*)d_in[4];
    const float* Wh1 = (const float*)d_in[5];
    const float* bh1 = (const float*)d_in[6];
    const float* Wh2 = (const float*)d_in[7];
    const float* bh2 = (const float*)d_in[8];
    float* out = (float*)d_out;

    static cudaStream_t s1 = nullptr;
    static cudaEvent_t evRoot = nullptr, evW12 = nullptr, evWh = nullptr;
    if (!s1) {
        cudaStreamCreateWithFlags(&s1, cudaStreamNonBlocking);
        cudaEventCreateWithFlags(&evRoot, cudaEventDisableTiming);
        cudaEventCreateWithFlags(&evW12, cudaEventDisableTiming);
        cudaEventCreateWithFlags(&evWh, cudaEventDisableTiming);
        cudaFuncSetAttribute(k_mm,   cudaFuncAttributeMaxDynamicSharedMemorySize, DSMEM_BYTES);
        cudaFuncSetAttribute(k_head, cudaFuncAttributeMaxDynamicSharedMemorySize, DSMEM_BYTES);
    }

    __nv_bfloat16 *xhi, *xlo, *l1hi, *l1lo, *l2hi, *l2lo;
    __nv_bfloat16 *w1hi, *w1lo, *w2hi, *w2lo, *whhi, *whlo;
    cudaGetSymbolAddress((void**)&xhi,  g_xhi);  cudaGetSymbolAddress((void**)&xlo,  g_xlo);
    cudaGetSymbolAddress((void**)&l1hi, g_l1hi); cudaGetSymbolAddress((void**)&l1lo, g_l1lo);
    cudaGetSymbolAddress((void**)&l2hi, g_l2hi); cudaGetSymbolAddress((void**)&l2lo, g_l2lo);
    cudaGetSymbolAddress((void**)&w1hi, g_w1hi); cudaGetSymbolAddress((void**)&w1lo, g_w1lo);
    cudaGetSymbolAddress((void**)&w2hi, g_w2hi); cudaGetSymbolAddress((void**)&w2lo, g_w2lo);
    cudaGetSymbolAddress((void**)&whhi, g_whhi); cudaGetSymbolAddress((void**)&whlo, g_whlo);

    // fork: weight conversion on side stream, overlapping prep + first GEMMs
    cudaEventRecord(evRoot, 0);
    cudaStreamWaitEvent(s1, evRoot, 0);
    k_convw<<<dim3(16, 16, 2), dim3(32, 8), 0, s1>>>(W1, W2, Wh1);   // W1 + W2
    cudaEventRecord(evW12, s1);
    {   // Wh1 only (shift z by 2 via pointer trickery: launch z=16 and treat all as Wh1)
        // reuse same kernel: pass Wh1 as all three, z>=2 path only; z 0/1 would clobber,
        // so launch a z-offset grid by passing W1/W2 pointers equal to Wh1 slices is unsafe.
        // Instead: full grid z=18 minus first two planes is not expressible; launch z=16
        // with a dedicated wrapper below.
    }
    k_convw<<<dim3(16, 16, 18), dim3(32, 8), 0, s1>>>(W1, W2, Wh1);  // full set incl. Wh1
    cudaEventRecord(evWh, s1);

    // main stream: zero + pack/bin
    k_zero<<<1, 32>>>();
    k_prep<<<B_DIM / 8, 256>>>(in, bh2, out);

    // join W1/W2 before first GEMM
    cudaStreamWaitEvent(0, evW12, 0);
    k_mm<<<dim3(B_DIM / 128, 4), 256, DSMEM_BYTES>>>(xhi, xlo, w1hi, w1lo, b1, l1hi, l1lo);
    k_mm<<<dim3(B_DIM / 128, 4), 256, DSMEM_BYTES>>>(l1hi, l1lo, w2hi, w2lo, b2, l2hi, l2lo);

    // join Wh1 before head
    cudaStreamWaitEvent(0, evWh, 0);
    k_head<<<dim3(128, 4, 16), 256, DSMEM_BYTES>>>(l2hi, l2lo, whhi, whlo, bh1, Wh2, out);
}

// round 5
// speedup vs baseline: 2.6042x; 1.0144x over previous
#include <cuda_runtime.h>
#include <cuda_bf16.h>
#include <cstdint>

#define B_DIM 16384
#define K_DIM 512
#define T_DIM 16
#define IN_STRIDE 513
#define DSMEM_BYTES (3 * 32768 + 128)

// ---------------- device scratch ----------------
__device__ __nv_bfloat16 g_xhi[B_DIM * K_DIM], g_xlo[B_DIM * K_DIM];
__device__ __nv_bfloat16 g_l1hi[B_DIM * K_DIM], g_l1lo[B_DIM * K_DIM];
__device__ __nv_bfloat16 g_l2hi[B_DIM * K_DIM], g_l2lo[B_DIM * K_DIM];
__device__ __nv_bfloat16 g_w1hi[K_DIM * K_DIM], g_w1lo[K_DIM * K_DIM];
__device__ __nv_bfloat16 g_w2hi[K_DIM * K_DIM], g_w2lo[K_DIM * K_DIM];
__device__ __nv_bfloat16 g_whhi[T_DIM * K_DIM * K_DIM], g_whlo[T_DIM * K_DIM * K_DIM];
__device__ int g_bins[T_DIM * B_DIM];
__device__ int g_cnt[T_DIM];

// ---------------- PTX helpers (sm_80-compatible) ----------------
__device__ __forceinline__ uint32_t smem_u32(const void* p) {
    uint32_t a;
    asm("{ .reg .u64 t; cvta.to.shared.u64 t, %1; cvt.u32.u64 %0, t; }" : "=r"(a) : "l"(p));
    return a;
}
__device__ __forceinline__ void cp16(uint32_t dst, const void* src) {
    asm volatile("cp.async.cg.shared.global [%0], [%1], 16;" :: "r"(dst), "l"(src));
}
__device__ __forceinline__ void cp_commit() { asm volatile("cp.async.commit_group;"); }
template <int N>
__device__ __forceinline__ void cp_wait() { asm volatile("cp.async.wait_group %0;" :: "n"(N)); }

__device__ __forceinline__ void ldsm4(uint32_t addr, uint32_t& r0, uint32_t& r1,
                                      uint32_t& r2, uint32_t& r3) {
    asm volatile("ldmatrix.sync.aligned.m8n8.x4.shared.b16 {%0,%1,%2,%3}, [%4];"
                 : "=r"(r0), "=r"(r1), "=r"(r2), "=r"(r3) : "r"(addr));
}
__device__ __forceinline__ void mma16816(float* c, uint32_t a0, uint32_t a1, uint32_t a2,
                                         uint32_t a3, uint32_t b0, uint32_t b1) {
    asm volatile(
        "mma.sync.aligned.m16n8k16.row.col.f32.bf16.bf16.f32 "
        "{%0,%1,%2,%3}, {%4,%5,%6,%7}, {%8,%9}, {%0,%1,%2,%3};"
        : "+f"(c[0]), "+f"(c[1]), "+f"(c[2]), "+f"(c[3])
        : "r"(a0), "r"(a1), "r"(a2), "r"(a3), "r"(b0), "r"(b1));
}

__device__ __forceinline__ uint32_t pack_bf2(__nv_bfloat16 a, __nv_bfloat16 b) {
    return (uint32_t)__bfloat16_as_ushort(a) | ((uint32_t)__bfloat16_as_ushort(b) << 16);
}

// XOR swizzle on 16B chunks: row stride 64B
__device__ __forceinline__ uint32_t swz(uint32_t base, uint32_t row, uint32_t ch) {
    return base + row * 64u + ((ch ^ ((row >> 1) & 3u)) << 4);
}

// ---------------- small prep kernels ----------------
__global__ void k_zero() {
    if (threadIdx.x < T_DIM) g_cnt[threadIdx.x] = 0;
}

// vectorized pack: 4 rows/block, 64 threads/row, 8 cols/thread
__global__ void __launch_bounds__(256) k_prep(const float* __restrict__ in,
                                              const float* __restrict__ bh2,
                                              float* __restrict__ out) {
    int r = blockIdx.x * 4 + (threadIdx.x >> 6);
    int c0 = (threadIdx.x & 63) * 8;
    const float* src = in + (size_t)r * IN_STRIDE + c0;
    float v[8];
#pragma unroll
    for (int i = 0; i < 8; i++) v[i] = src[i];
    uint32_t hp[4], lp[4];
#pragma unroll
    for (int i = 0; i < 4; i++) {
        __nv_bfloat16 h0 = __float2bfloat16(v[2 * i]);
        __nv_bfloat16 h1 = __float2bfloat16(v[2 * i + 1]);
        __nv_bfloat16 l0 = __float2bfloat16(v[2 * i]     - __bfloat162float(h0));
        __nv_bfloat16 l1 = __float2bfloat16(v[2 * i + 1] - __bfloat162float(h1));
        hp[i] = pack_bf2(h0, h1);
        lp[i] = pack_bf2(l0, l1);
    }
    size_t o = (size_t)r * K_DIM + c0;
    *(uint4*)(g_xhi + o) = make_uint4(hp[0], hp[1], hp[2], hp[3]);
    *(uint4*)(g_xlo + o) = make_uint4(lp[0], lp[1], lp[2], lp[3]);
    if ((threadIdx.x & 63) == 0) {
        int t = (int)in[(size_t)r * IN_STRIDE + K_DIM];
        int pos = atomicAdd(&g_cnt[t], 1);
        g_bins[t * B_DIM + pos] = r;
        out[r] = bh2[t];
    }
}

// transpose+split weights; zeff = blockIdx.z + zbase: 0 -> W1, 1 -> W2, >=2 -> Wh1[zeff-2]
__global__ void k_convw(const float* __restrict__ W1, const float* __restrict__ W2,
                        const float* __restrict__ Wh1, int zbase) {
    __shared__ float tile[32][33];
    int z = blockIdx.z + zbase;
    const float* Wm;
    __nv_bfloat16 *hi, *lo;
    size_t obase;
    if (z == 0)      { Wm = W1; hi = g_w1hi; lo = g_w1lo; obase = 0; }
    else if (z == 1) { Wm = W2; hi = g_w2hi; lo = g_w2lo; obase = 0; }
    else {
        int mat = z - 2;
        Wm = Wh1 + (size_t)mat * K_DIM * K_DIM;
        hi = g_whhi; lo = g_whlo;
        obase = (size_t)mat * K_DIM * K_DIM;
    }
    int k0 = blockIdx.x * 32, n0 = blockIdx.y * 32;
    for (int ky = threadIdx.y; ky < 32; ky += 8)
        tile[ky][threadIdx.x] = Wm[(size_t)(k0 + ky) * K_DIM + n0 + threadIdx.x];
    __syncthreads();
    for (int ny = threadIdx.y; ny < 32; ny += 8) {
        float v = tile[threadIdx.x][ny];
        __nv_bfloat16 h = __float2bfloat16(v);
        size_t o = obase + (size_t)(n0 + ny) * K_DIM + k0 + threadIdx.x;
        hi[o] = h;
        lo[o] = __float2bfloat16(v - __bfloat162float(h));
    }
}

// ---------------- tile loads: 4 sub-tiles (Ahi,Alo,Bhi,Blo), each 128x32 bf16 ----------------
__device__ __forceinline__ void issue_chunk(
    uint32_t sbuf, int stage, int k0, const int* __restrict__ rows_s, int bn0,
    const __nv_bfloat16* __restrict__ Ahi, const __nv_bfloat16* __restrict__ Alo,
    const __nv_bfloat16* __restrict__ Bhi, const __nv_bfloat16* __restrict__ Blo, int tid) {
    uint32_t sb = sbuf + (uint32_t)stage * 32768u;
#pragma unroll
    for (int i = 0; i < 8; i++) {
        int idx = tid + i * 256;
        int tile = idx >> 9, w = idx & 511, row = w >> 2, ch = w & 3;
        const __nv_bfloat16* src;
        int gr;
        if (tile == 0)      { src = Ahi; gr = rows_s[row]; }
        else if (tile == 1) { src = Alo; gr = rows_s[row]; }
        else if (tile == 2) { src = Bhi; gr = bn0 + row; }
        else                { src = Blo; gr = bn0 + row; }
        cp16(swz(sb + (uint32_t)tile * 8192u, (uint32_t)row, (uint32_t)ch),
             src + (size_t)gr * K_DIM + k0 + ch * 8);
    }
    cp_commit();
}

// ---------------- per-chunk MMA: 3 passes (hi*hi, hi*lo, lo*hi) ----------------
__device__ __forceinline__ void compute_chunk(float acc[4][4][4], uint32_t sbuf, int stage,
                                              int lane, int wm, int wn) {
    uint32_t sb = sbuf + (uint32_t)stage * 32768u;
    uint32_t A_hi = sb, A_lo = sb + 8192u, B_hi = sb + 16384u, B_lo = sb + 24576u;
    uint32_t lrow = (uint32_t)(lane & 15);
    uint32_t lsel = (uint32_t)(lane >> 4);
#pragma unroll
    for (int kk = 0; kk < 2; kk++) {
        uint32_t ch = (uint32_t)(kk * 2) + lsel;
        uint32_t ah[4][4], bb[2][4], b2[2][4];
#pragma unroll
        for (int im = 0; im < 4; im++)
            ldsm4(swz(A_hi, (uint32_t)(wm * 64 + im * 16) + lrow, ch),
                  ah[im][0], ah[im][1], ah[im][2], ah[im][3]);
#pragma unroll
        for (int jn = 0; jn < 2; jn++)
            ldsm4(swz(B_hi, (uint32_t)(wn * 32 + jn * 16) + lrow, ch),
                  bb[jn][0], bb[jn][1], bb[jn][2], bb[jn][3]);
#pragma unroll
        for (int im = 0; im < 4; im++)
#pragma unroll
            for (int j = 0; j < 4; j++)
                mma16816(acc[im][j], ah[im][0], ah[im][1], ah[im][2], ah[im][3],
                         bb[j >> 1][j & 1], bb[j >> 1][(j & 1) + 2]);
#pragma unroll
        for (int jn = 0; jn < 2; jn++)
            ldsm4(swz(B_lo, (uint32_t)(wn * 32 + jn * 16) + lrow, ch),
                  b2[jn][0], b2[jn][1], b2[jn][2], b2[jn][3]);
#pragma unroll
        for (int im = 0; im < 4; im++)
#pragma unroll
            for (int j = 0; j < 4; j++)
                mma16816(acc[im][j], ah[im][0], ah[im][1], ah[im][2], ah[im][3],
                         b2[j >> 1][j & 1], b2[j >> 1][(j & 1) + 2]);
#pragma unroll
        for (int im = 0; im < 4; im++)
            ldsm4(swz(A_lo, (uint32_t)(wm * 64 + im * 16) + lrow, ch),
                  ah[im][0], ah[im][1], ah[im][2], ah[im][3]);
#pragma unroll
        for (int im = 0; im < 4; im++)
#pragma unroll
            for (int j = 0; j < 4; j++)
                mma16816(acc[im][j], ah[im][0], ah[im][1], ah[im][2], ah[im][3],
                         bb[j >> 1][j & 1], bb[j >> 1][(j & 1) + 2]);
    }
}

// 3-stage pipeline, one barrier per iteration.
__device__ __forceinline__ void mma_mainloop(
    float acc[4][4][4], uint32_t sbuf, const int* __restrict__ rows_s, int bn0,
    const __nv_bfloat16* __restrict__ Ahi, const __nv_bfloat16* __restrict__ Alo,
    const __nv_bfloat16* __restrict__ Bhi, const __nv_bfloat16* __restrict__ Blo,
    int tid, int lane, int wm, int wn) {
    issue_chunk(sbuf, 0, 0, rows_s, bn0, Ahi, Alo, Bhi, Blo, tid);
    issue_chunk(sbuf, 1, 32, rows_s, bn0, Ahi, Alo, Bhi, Blo, tid);
    int stage = 0;
#pragma unroll 1
    for (int c = 0; c < 16; c++) {
        if (c >= 14) cp_wait<0>(); else cp_wait<1>();
        __syncthreads();
        if (c + 2 < 16) {
            int ns = stage + 2; if (ns >= 3) ns -= 3;
            issue_chunk(sbuf, ns, (c + 2) * 32, rows_s, bn0, Ahi, Alo, Bhi, Blo, tid);
        }
        compute_chunk(acc, sbuf, stage, lane, wm, wn);
        if (++stage == 3) stage = 0;
    }
}

// ---------------- GEMM + bias + relu -> bf16 hi/lo ----------------
__global__ void __launch_bounds__(256) k_mm(
    const __nv_bfloat16* __restrict__ Ahi, const __nv_bfloat16* __restrict__ Alo,
    const __nv_bfloat16* __restrict__ Bhi, const __nv_bfloat16* __restrict__ Blo,
    const float* __restrict__ bias,
    __nv_bfloat16* __restrict__ Chi, __nv_bfloat16* __restrict__ Clo) {
    extern __shared__ char dsmem[];
    __shared__ int rows_s[128];
    __shared__ float sbias[128];
    uint32_t sbuf = (smem_u32(dsmem) + 127u) & ~127u;

    int tid = threadIdx.x, lane = tid & 31, wid = tid >> 5;
    int wm = wid & 1, wn = wid >> 1;
    int m0 = blockIdx.x * 128, n0 = blockIdx.y * 128;

    if (tid < 128) { rows_s[tid] = m0 + tid; sbias[tid] = bias[n0 + tid]; }
    __syncthreads();

    float acc[4][4][4];
#pragma unroll
    for (int a = 0; a < 4; a++)
#pragma unroll
        for (int b = 0; b < 4; b++)
#pragma unroll
            for (int d = 0; d < 4; d++) acc[a][b][d] = 0.f;

    mma_mainloop(acc, sbuf, rows_s, n0, Ahi, Alo, Bhi, Blo, tid, lane, wm, wn);

#pragma unroll
    for (int im = 0; im < 4; im++) {
        int r0 = m0 + wm * 64 + im * 16 + (lane >> 2);
#pragma unroll
        for (int j = 0; j < 4; j++) {
            int nloc = wn * 32 + j * 8 + (lane & 3) * 2;
            float v0 = fmaxf(acc[im][j][0] + sbias[nloc],     0.f);
            float v1 = fmaxf(acc[im][j][1] + sbias[nloc + 1], 0.f);
            float v2 = fmaxf(acc[im][j][2] + sbias[nloc],     0.f);
            float v3 = fmaxf(acc[im][j][3] + sbias[nloc + 1], 0.f);
            __nv_bfloat16 h0 = __float2bfloat16(v0), h1 = __float2bfloat16(v1);
            __nv_bfloat16 h2 = __float2bfloat16(v2), h3 = __float2bfloat16(v3);
            __nv_bfloat16 l0 = __float2bfloat16(v0 - __bfloat162float(h0));
            __nv_bfloat16 l1 = __float2bfloat16(v1 - __bfloat162float(h1));
            __nv_bfloat16 l2 = __float2bfloat16(v2 - __bfloat162float(h2));
            __nv_bfloat16 l3 = __float2bfloat16(v3 - __bfloat162float(h3));
            size_t o0 = (size_t)r0 * K_DIM + n0 + nloc;
            size_t o1 = (size_t)(r0 + 8) * K_DIM + n0 + nloc;
            *(uint32_t*)(Chi + o0) = pack_bf2(h0, h1);
            *(uint32_t*)(Chi + o1) = pack_bf2(h2, h3);
            *(uint32_t*)(Clo + o0) = pack_bf2(l0, l1);
            *(uint32_t*)(Clo + o1) = pack_bf2(l2, l3);
        }
    }
}

// ---------------- head: gathered GEMM + relu + dot(Wh2) reduce ----------------
__global__ void __launch_bounds__(256) k_head(
    const __nv_bfloat16* __restrict__ l2hi, const __nv_bfloat16* __restrict__ l2lo,
    const __nv_bfloat16* __restrict__ whhi, const __nv_bfloat16* __restrict__ whlo,
    const float* __restrict__ bh1, const float* __restrict__ Wh2,
    float* __restrict__ out) {
    int t = blockIdx.z;
    int cnt = g_cnt[t];
    int tile = blockIdx.x;
    if (tile * 128 >= cnt) return;
    int n0 = blockIdx.y * 128;

    extern __shared__ char dsmem[];
    __shared__ int rows_s[128];
    __shared__ float sbh1[128];
    __shared__ float swh2[128];
    uint32_t sbuf = (smem_u32(dsmem) + 127u) & ~127u;

    int tid = threadIdx.x, lane = tid & 31, wid = tid >> 5;
    int wm = wid & 1, wn = wid >> 1;

    if (tid < 128) {
        int idx = tile * 128 + tid;
        rows_s[tid] = g_bins[t * B_DIM + (idx < cnt ? idx : cnt - 1)];
        sbh1[tid] = bh1[t * K_DIM + n0 + tid];
        swh2[tid] = Wh2[t * K_DIM + n0 + tid];
    }
    __syncthreads();

    float acc[4][4][4];
#pragma unroll
    for (int a = 0; a < 4; a++)
#pragma unroll
        for (int b = 0; b < 4; b++)
#pragma unroll
            for (int d = 0; d < 4; d++) acc[a][b][d] = 0.f;

    mma_mainloop(acc, sbuf, rows_s, n0,
                 l2hi, l2lo,
                 whhi + (size_t)t * K_DIM * K_DIM, whlo + (size_t)t * K_DIM * K_DIM,
                 tid, lane, wm, wn);

#pragma unroll
    for (int im = 0; im < 4; im++) {
        float p0 = 0.f, p1 = 0.f;
#pragma unroll
        for (int j = 0; j < 4; j++) {
            int nloc = wn * 32 + j * 8 + (lane & 3) * 2;
            float w0 = swh2[nloc], w1 = swh2[nloc + 1];
            float q0 = sbh1[nloc], q1 = sbh1[nloc + 1];
            p0 = fmaf(fmaxf(acc[im][j][0] + q0, 0.f), w0, p0);
            p0 = fmaf(fmaxf(acc[im][j][1] + q1, 0.f), w1, p0);
            p1 = fmaf(fmaxf(acc[im][j][2] + q0, 0.f), w0, p1);
            p1 = fmaf(fmaxf(acc[im][j][3] + q1, 0.f), w1, p1);
        }
        p0 += __shfl_xor_sync(0xffffffffu, p0, 1);
        p0 += __shfl_xor_sync(0xffffffffu, p0, 2);
        p1 += __shfl_xor_sync(0xffffffffu, p1, 1);
        p1 += __shfl_xor_sync(0xffffffffu, p1, 2);
        if ((lane & 3) == 0) {
            int rl0 = wm * 64 + im * 16 + (lane >> 2);
            int rl1 = rl0 + 8;
            if (tile * 128 + rl0 < cnt) atomicAdd(&out[rows_s[rl0]], p0);
            if (tile * 128 + rl1 < cnt) atomicAdd(&out[rows_s[rl1]], p1);
        }
    }
}

// ---------------- launch ----------------
extern "C" void kernel_launch(void* const* d_in, const int* in_sizes, int n_in,
                              void* d_out, int out_size) {
    const float* in  = (const float*)d_in[0];
    const float* W1  = (const float*)d_in[1];
    const float* b1  = (const float*)d_in[2];
    const float* W2  = (const float*)d_in[3];
    const float* b2  = (const float*)d_in[4];
    const float* Wh1 = (const float*)d_in[5];
    const float* bh1 = (const float*)d_in[6];
    const float* Wh2 = (const float*)d_in[7];
    const float* bh2 = (const float*)d_in[8];
    float* out = (float*)d_out;

    static cudaStream_t s1 = nullptr;
    static cudaEvent_t evRoot = nullptr, evW12 = nullptr, evWh = nullptr;
    if (!s1) {
        cudaStreamCreateWithFlags(&s1, cudaStreamNonBlocking);
        cudaEventCreateWithFlags(&evRoot, cudaEventDisableTiming);
        cudaEventCreateWithFlags(&evW12, cudaEventDisableTiming);
        cudaEventCreateWithFlags(&evWh, cudaEventDisableTiming);
        cudaFuncSetAttribute(k_mm,   cudaFuncAttributeMaxDynamicSharedMemorySize, DSMEM_BYTES);
        cudaFuncSetAttribute(k_head, cudaFuncAttributeMaxDynamicSharedMemorySize, DSMEM_BYTES);
    }

    __nv_bfloat16 *xhi, *xlo, *l1hi, *l1lo, *l2hi, *l2lo;
    __nv_bfloat16 *w1hi, *w1lo, *w2hi, *w2lo, *whhi, *whlo;
    cudaGetSymbolAddress((void**)&xhi,  g_xhi);  cudaGetSymbolAddress((void**)&xlo,  g_xlo);
    cudaGetSymbolAddress((void**)&l1hi, g_l1hi); cudaGetSymbolAddress((void**)&l1lo, g_l1lo);
    cudaGetSymbolAddress((void**)&l2hi, g_l2hi); cudaGetSymbolAddress((void**)&l2lo, g_l2lo);
    cudaGetSymbolAddress((void**)&w1hi, g_w1hi); cudaGetSymbolAddress((void**)&w1lo, g_w1lo);
    cudaGetSymbolAddress((void**)&w2hi, g_w2hi); cudaGetSymbolAddress((void**)&w2lo, g_w2lo);
    cudaGetSymbolAddress((void**)&whhi, g_whhi); cudaGetSymbolAddress((void**)&whlo, g_whlo);

    // fork: weight conversion on side stream (W1/W2 first, then Wh1)
    cudaEventRecord(evRoot, 0);
    cudaStreamWaitEvent(s1, evRoot, 0);
    k_convw<<<dim3(16, 16, 2),  dim3(32, 8), 0, s1>>>(W1, W2, Wh1, 0);  // W1, W2
    cudaEventRecord(evW12, s1);
    k_convw<<<dim3(16, 16, 16), dim3(32, 8), 0, s1>>>(W1, W2, Wh1, 2);  // Wh1 only
    cudaEventRecord(evWh, s1);

    // main stream: zero + pack/bin
    k_zero<<<1, 32>>>();
    k_prep<<<B_DIM / 4, 256>>>(in, bh2, out);

    // join W1/W2 before first GEMM
    cudaStreamWaitEvent(0, evW12, 0);
    k_mm<<<dim3(B_DIM / 128, 4), 256, DSMEM_BYTES>>>(xhi, xlo, w1hi, w1lo, b1, l1hi, l1lo);
    k_mm<<<dim3(B_DIM / 128, 4), 256, DSMEM_BYTES>>>(l1hi, l1lo, w2hi, w2lo, b2, l2hi, l2lo);

    // join Wh1 before head
    cudaStreamWaitEvent(0, evWh, 0);
    k_head<<<dim3(128, 4, 16), 256, DSMEM_BYTES>>>(l2hi, l2lo, whhi, whlo, bh1, Wh2, out);
}

// round 6
// speedup vs baseline: 3.2229x; 1.2376x over previous
#include <cuda_runtime.h>
#include <cuda_fp16.h>
#include <cstdint>

#define B_DIM 16384
#define K_DIM 512
#define T_DIM 16
#define IN_STRIDE 513
#define STAGE_BYTES 24576
#define DSMEM_BYTES (3 * STAGE_BYTES + 128)

// ---------------- device scratch (fp16 split: activations hi+lo, weights hi only) ----------------
__device__ __half g_xh[B_DIM * K_DIM],  g_xl[B_DIM * K_DIM];
__device__ __half g_l1h[B_DIM * K_DIM], g_l1l[B_DIM * K_DIM];
__device__ __half g_l2h[B_DIM * K_DIM], g_l2l[B_DIM * K_DIM];
__device__ __half g_w1h[K_DIM * K_DIM];
__device__ __half g_w2h[K_DIM * K_DIM];
__device__ __half g_whh[T_DIM * K_DIM * K_DIM];
__device__ int g_bins[T_DIM * B_DIM];
__device__ int g_cnt[T_DIM];

// ---------------- PTX helpers (sm_80-compatible) ----------------
__device__ __forceinline__ uint32_t smem_u32(const void* p) {
    uint32_t a;
    asm("{ .reg .u64 t; cvta.to.shared.u64 t, %1; cvt.u32.u64 %0, t; }" : "=r"(a) : "l"(p));
    return a;
}
__device__ __forceinline__ void cp16(uint32_t dst, const void* src) {
    asm volatile("cp.async.cg.shared.global [%0], [%1], 16;" :: "r"(dst), "l"(src));
}
__device__ __forceinline__ void cp_commit() { asm volatile("cp.async.commit_group;"); }
template <int N>
__device__ __forceinline__ void cp_wait() { asm volatile("cp.async.wait_group %0;" :: "n"(N)); }

__device__ __forceinline__ void ldsm4(uint32_t addr, uint32_t& r0, uint32_t& r1,
                                      uint32_t& r2, uint32_t& r3) {
    asm volatile("ldmatrix.sync.aligned.m8n8.x4.shared.b16 {%0,%1,%2,%3}, [%4];"
                 : "=r"(r0), "=r"(r1), "=r"(r2), "=r"(r3) : "r"(addr));
}
__device__ __forceinline__ void mma16816(float* c, uint32_t a0, uint32_t a1, uint32_t a2,
                                         uint32_t a3, uint32_t b0, uint32_t b1) {
    asm volatile(
        "mma.sync.aligned.m16n8k16.row.col.f32.f16.f16.f32 "
        "{%0,%1,%2,%3}, {%4,%5,%6,%7}, {%8,%9}, {%0,%1,%2,%3};"
        : "+f"(c[0]), "+f"(c[1]), "+f"(c[2]), "+f"(c[3])
        : "r"(a0), "r"(a1), "r"(a2), "r"(a3), "r"(b0), "r"(b1));
}

__device__ __forceinline__ uint32_t pack_h2(__half a, __half b) {
    return (uint32_t)__half_as_ushort(a) | ((uint32_t)__half_as_ushort(b) << 16);
}

// XOR swizzle on 16B chunks: row stride 64B
__device__ __forceinline__ uint32_t swz(uint32_t base, uint32_t row, uint32_t ch) {
    return base + row * 64u + ((ch ^ ((row >> 1) & 3u)) << 4);
}

// ---------------- small prep kernels ----------------
__global__ void k_zero() {
    if (threadIdx.x < T_DIM) g_cnt[threadIdx.x] = 0;
}

// vectorized pack: 4 rows/block, 64 threads/row, 8 cols/thread; fp16 hi/lo split
__global__ void __launch_bounds__(256) k_prep(const float* __restrict__ in,
                                              const float* __restrict__ bh2,
                                              float* __restrict__ out) {
    int r = blockIdx.x * 4 + (threadIdx.x >> 6);
    int c0 = (threadIdx.x & 63) * 8;
    const float* src = in + (size_t)r * IN_STRIDE + c0;
    float v[8];
#pragma unroll
    for (int i = 0; i < 8; i++) v[i] = src[i];
    uint32_t hp[4], lp[4];
#pragma unroll
    for (int i = 0; i < 4; i++) {
        __half h0 = __float2half(v[2 * i]);
        __half h1 = __float2half(v[2 * i + 1]);
        __half l0 = __float2half(v[2 * i]     - __half2float(h0));
        __half l1 = __float2half(v[2 * i + 1] - __half2float(h1));
        hp[i] = pack_h2(h0, h1);
        lp[i] = pack_h2(l0, l1);
    }
    size_t o = (size_t)r * K_DIM + c0;
    *(uint4*)(g_xh + o) = make_uint4(hp[0], hp[1], hp[2], hp[3]);
    *(uint4*)(g_xl + o) = make_uint4(lp[0], lp[1], lp[2], lp[3]);
    if ((threadIdx.x & 63) == 0) {
        int t = (int)in[(size_t)r * IN_STRIDE + K_DIM];
        int pos = atomicAdd(&g_cnt[t], 1);
        g_bins[t * B_DIM + pos] = r;
        out[r] = bh2[t];
    }
}

// transpose weights [K,N] fp32 -> [N,K] fp16; zeff: 0 -> W1, 1 -> W2, >=2 -> Wh1[zeff-2]
__global__ void k_convw(const float* __restrict__ W1, const float* __restrict__ W2,
                        const float* __restrict__ Wh1, int zbase) {
    __shared__ float tile[32][33];
    int z = blockIdx.z + zbase;
    const float* Wm;
    __half* hi;
    size_t obase;
    if (z == 0)      { Wm = W1; hi = g_w1h; obase = 0; }
    else if (z == 1) { Wm = W2; hi = g_w2h; obase = 0; }
    else {
        int mat = z - 2;
        Wm = Wh1 + (size_t)mat * K_DIM * K_DIM;
        hi = g_whh;
        obase = (size_t)mat * K_DIM * K_DIM;
    }
    int k0 = blockIdx.x * 32, n0 = blockIdx.y * 32;
    for (int ky = threadIdx.y; ky < 32; ky += 8)
        tile[ky][threadIdx.x] = Wm[(size_t)(k0 + ky) * K_DIM + n0 + threadIdx.x];
    __syncthreads();
    for (int ny = threadIdx.y; ny < 32; ny += 8) {
        float v = tile[threadIdx.x][ny];
        hi[obase + (size_t)(n0 + ny) * K_DIM + k0 + threadIdx.x] = __float2half(v);
    }
}

// ---------------- tile loads: 3 sub-tiles (Ahi, Alo, Whi), each 128x32 fp16 ----------------
__device__ __forceinline__ void issue_chunk(
    uint32_t sbuf, int stage, int k0, const int* __restrict__ rows_s, int bn0,
    const __half* __restrict__ Ahi, const __half* __restrict__ Alo,
    const __half* __restrict__ Bhi, int tid) {
    uint32_t sb = sbuf + (uint32_t)stage * (uint32_t)STAGE_BYTES;
#pragma unroll
    for (int i = 0; i < 6; i++) {
        int idx = tid + i * 256;
        int tile = idx >> 9, w = idx & 511, row = w >> 2, ch = w & 3;
        const __half* src;
        int gr;
        if (tile == 0)      { src = Ahi; gr = rows_s[row]; }
        else if (tile == 1) { src = Alo; gr = rows_s[row]; }
        else                { src = Bhi; gr = bn0 + row; }
        cp16(swz(sb + (uint32_t)tile * 8192u, (uint32_t)row, (uint32_t)ch),
             src + (size_t)gr * K_DIM + k0 + ch * 8);
    }
    cp_commit();
}

// ---------------- per-chunk MMA: 2 passes (Ahi*Whi, Alo*Whi) ----------------
__device__ __forceinline__ void compute_chunk(float acc[4][4][4], uint32_t sbuf, int stage,
                                              int lane, int wm, int wn) {
    uint32_t sb = sbuf + (uint32_t)stage * (uint32_t)STAGE_BYTES;
    uint32_t A_hi = sb, A_lo = sb + 8192u, B_hi = sb + 16384u;
    uint32_t lrow = (uint32_t)(lane & 15);
    uint32_t lsel = (uint32_t)(lane >> 4);
#pragma unroll
    for (int kk = 0; kk < 2; kk++) {
        uint32_t ch = (uint32_t)(kk * 2) + lsel;
        uint32_t ah[4][4], bb[2][4];
#pragma unroll
        for (int im = 0; im < 4; im++)
            ldsm4(swz(A_hi, (uint32_t)(wm * 64 + im * 16) + lrow, ch),
                  ah[im][0], ah[im][1], ah[im][2], ah[im][3]);
#pragma unroll
        for (int jn = 0; jn < 2; jn++)
            ldsm4(swz(B_hi, (uint32_t)(wn * 32 + jn * 16) + lrow, ch),
                  bb[jn][0], bb[jn][1], bb[jn][2], bb[jn][3]);
        // pass 0: Ahi * Whi
#pragma unroll
        for (int im = 0; im < 4; im++)
#pragma unroll
            for (int j = 0; j < 4; j++)
                mma16816(acc[im][j], ah[im][0], ah[im][1], ah[im][2], ah[im][3],
                         bb[j >> 1][j & 1], bb[j >> 1][(j & 1) + 2]);
        // pass 1: Alo * Whi (reuse B fragments)
#pragma unroll
        for (int im = 0; im < 4; im++)
            ldsm4(swz(A_lo, (uint32_t)(wm * 64 + im * 16) + lrow, ch),
                  ah[im][0], ah[im][1], ah[im][2], ah[im][3]);
#pragma unroll
        for (int im = 0; im < 4; im++)
#pragma unroll
            for (int j = 0; j < 4; j++)
                mma16816(acc[im][j], ah[im][0], ah[im][1], ah[im][2], ah[im][3],
                         bb[j >> 1][j & 1], bb[j >> 1][(j & 1) + 2]);
    }
}

// 3-stage pipeline, one barrier per iteration.
__device__ __forceinline__ void mma_mainloop(
    float acc[4][4][4], uint32_t sbuf, const int* __restrict__ rows_s, int bn0,
    const __half* __restrict__ Ahi, const __half* __restrict__ Alo,
    const __half* __restrict__ Bhi, int tid, int lane, int wm, int wn) {
    issue_chunk(sbuf, 0, 0, rows_s, bn0, Ahi, Alo, Bhi, tid);
    issue_chunk(sbuf, 1, 32, rows_s, bn0, Ahi, Alo, Bhi, tid);
    int stage = 0;
#pragma unroll 1
    for (int c = 0; c < 16; c++) {
        if (c >= 14) cp_wait<0>(); else cp_wait<1>();
        __syncthreads();
        if (c + 2 < 16) {
            int ns = stage + 2; if (ns >= 3) ns -= 3;
            issue_chunk(sbuf, ns, (c + 2) * 32, rows_s, bn0, Ahi, Alo, Bhi, tid);
        }
        compute_chunk(acc, sbuf, stage, lane, wm, wn);
        if (++stage == 3) stage = 0;
    }
}

// ---------------- GEMM + bias + relu -> fp16 hi/lo ----------------
__global__ void __launch_bounds__(256) k_mm(
    const __half* __restrict__ Ahi, const __half* __restrict__ Alo,
    const __half* __restrict__ Bhi, const float* __restrict__ bias,
    __half* __restrict__ Chi, __half* __restrict__ Clo) {
    extern __shared__ char dsmem[];
    __shared__ int rows_s[128];
    __shared__ float sbias[128];
    uint32_t sbuf = (smem_u32(dsmem) + 127u) & ~127u;

    int tid = threadIdx.x, lane = tid & 31, wid = tid >> 5;
    int wm = wid & 1, wn = wid >> 1;
    int m0 = blockIdx.x * 128, n0 = blockIdx.y * 128;

    if (tid < 128) { rows_s[tid] = m0 + tid; sbias[tid] = bias[n0 + tid]; }
    __syncthreads();

    float acc[4][4][4];
#pragma unroll
    for (int a = 0; a < 4; a++)
#pragma unroll
        for (int b = 0; b < 4; b++)
#pragma unroll
            for (int d = 0; d < 4; d++) acc[a][b][d] = 0.f;

    mma_mainloop(acc, sbuf, rows_s, n0, Ahi, Alo, Bhi, tid, lane, wm, wn);

#pragma unroll
    for (int im = 0; im < 4; im++) {
        int r0 = m0 + wm * 64 + im * 16 + (lane >> 2);
#pragma unroll
        for (int j = 0; j < 4; j++) {
            int nloc = wn * 32 + j * 8 + (lane & 3) * 2;
            float v0 = fmaxf(acc[im][j][0] + sbias[nloc],     0.f);
            float v1 = fmaxf(acc[im][j][1] + sbias[nloc + 1], 0.f);
            float v2 = fmaxf(acc[im][j][2] + sbias[nloc],     0.f);
            float v3 = fmaxf(acc[im][j][3] + sbias[nloc + 1], 0.f);
            __half h0 = __float2half(v0), h1 = __float2half(v1);
            __half h2 = __float2half(v2), h3 = __float2half(v3);
            __half l0 = __float2half(v0 - __half2float(h0));
            __half l1 = __float2half(v1 - __half2float(h1));
            __half l2 = __float2half(v2 - __half2float(h2));
            __half l3 = __float2half(v3 - __half2float(h3));
            size_t o0 = (size_t)r0 * K_DIM + n0 + nloc;
            size_t o1 = (size_t)(r0 + 8) * K_DIM + n0 + nloc;
            *(uint32_t*)(Chi + o0) = pack_h2(h0, h1);
            *(uint32_t*)(Chi + o1) = pack_h2(h2, h3);
            *(uint32_t*)(Clo + o0) = pack_h2(l0, l1);
            *(uint32_t*)(Clo + o1) = pack_h2(l2, l3);
        }
    }
}

// ---------------- head: gathered GEMM + relu + dot(Wh2) reduce ----------------
__global__ void __launch_bounds__(256) k_head(
    const __half* __restrict__ l2h, const __half* __restrict__ l2l,
    const __half* __restrict__ whh,
    const float* __restrict__ bh1, const float* __restrict__ Wh2,
    float* __restrict__ out) {
    int t = blockIdx.z;
    int cnt = g_cnt[t];
    int tile = blockIdx.x;
    if (tile * 128 >= cnt) return;
    int n0 = blockIdx.y * 128;

    extern __shared__ char dsmem[];
    __shared__ int rows_s[128];
    __shared__ float sbh1[128];
    __shared__ float swh2[128];
    uint32_t sbuf = (smem_u32(dsmem) + 127u) & ~127u;

    int tid = threadIdx.x, lane = tid & 31, wid = tid >> 5;
    int wm = wid & 1, wn = wid >> 1;

    if (tid < 128) {
        int idx = tile * 128 + tid;
        rows_s[tid] = g_bins[t * B_DIM + (idx < cnt ? idx : cnt - 1)];
        sbh1[tid] = bh1[t * K_DIM + n0 + tid];
        swh2[tid] = Wh2[t * K_DIM + n0 + tid];
    }
    __syncthreads();

    float acc[4][4][4];
#pragma unroll
    for (int a = 0; a < 4; a++)
#pragma unroll
        for (int b = 0; b < 4; b++)
#pragma unroll
            for (int d = 0; d < 4; d++) acc[a][b][d] = 0.f;

    mma_mainloop(acc, sbuf, rows_s, n0, l2h, l2l,
                 whh + (size_t)t * K_DIM * K_DIM, tid, lane, wm, wn);

#pragma unroll
    for (int im = 0; im < 4; im++) {
        float p0 = 0.f, p1 = 0.f;
#pragma unroll
        for (int j = 0; j < 4; j++) {
            int nloc = wn * 32 + j * 8 + (lane & 3) * 2;
            float w0 = swh2[nloc], w1 = swh2[nloc + 1];
            float q0 = sbh1[nloc], q1 = sbh1[nloc + 1];
            p0 = fmaf(fmaxf(acc[im][j][0] + q0, 0.f), w0, p0);
            p0 = fmaf(fmaxf(acc[im][j][1] + q1, 0.f), w1, p0);
            p1 = fmaf(fmaxf(acc[im][j][2] + q0, 0.f), w0, p1);
            p1 = fmaf(fmaxf(acc[im][j][3] + q1, 0.f), w1, p1);
        }
        p0 += __shfl_xor_sync(0xffffffffu, p0, 1);
        p0 += __shfl_xor_sync(0xffffffffu, p0, 2);
        p1 += __shfl_xor_sync(0xffffffffu, p1, 1);
        p1 += __shfl_xor_sync(0xffffffffu, p1, 2);
        if ((lane & 3) == 0) {
            int rl0 = wm * 64 + im * 16 + (lane >> 2);
            int rl1 = rl0 + 8;
            if (tile * 128 + rl0 < cnt) atomicAdd(&out[rows_s[rl0]], p0);
            if (tile * 128 + rl1 < cnt) atomicAdd(&out[rows_s[rl1]], p1);
        }
    }
}

// ---------------- launch ----------------
extern "C" void kernel_launch(void* const* d_in, const int* in_sizes, int n_in,
                              void* d_out, int out_size) {
    const float* in  = (const float*)d_in[0];
    const float* W1  = (const float*)d_in[1];
    const float* b1  = (const float*)d_in[2];
    const float* W2  = (const float*)d_in[3];
    const float* b2  = (const float*)d_in[4];
    const float* Wh1 = (const float*)d_in[5];
    const float* bh1 = (const float*)d_in[6];
    const float* Wh2 = (const float*)d_in[7];
    const float* bh2 = (const float*)d_in[8];
    float* out = (float*)d_out;

    static cudaStream_t s1 = nullptr;
    static cudaEvent_t evRoot = nullptr, evW12 = nullptr, evWh = nullptr;
    if (!s1) {
        cudaStreamCreateWithFlags(&s1, cudaStreamNonBlocking);
        cudaEventCreateWithFlags(&evRoot, cudaEventDisableTiming);
        cudaEventCreateWithFlags(&evW12, cudaEventDisableTiming);
        cudaEventCreateWithFlags(&evWh, cudaEventDisableTiming);
        cudaFuncSetAttribute(k_mm,   cudaFuncAttributeMaxDynamicSharedMemorySize, DSMEM_BYTES);
        cudaFuncSetAttribute(k_head, cudaFuncAttributeMaxDynamicSharedMemorySize, DSMEM_BYTES);
    }

    __half *xh, *xl, *l1h, *l1l, *l2h, *l2l, *w1h, *w2h, *whh;
    cudaGetSymbolAddress((void**)&xh,  g_xh);  cudaGetSymbolAddress((void**)&xl,  g_xl);
    cudaGetSymbolAddress((void**)&l1h, g_l1h); cudaGetSymbolAddress((void**)&l1l, g_l1l);
    cudaGetSymbolAddress((void**)&l2h, g_l2h); cudaGetSymbolAddress((void**)&l2l, g_l2l);
    cudaGetSymbolAddress((void**)&w1h, g_w1h); cudaGetSymbolAddress((void**)&w2h, g_w2h);
    cudaGetSymbolAddress((void**)&whh, g_whh);

    // fork: weight conversion on side stream (W1/W2 first, then Wh1)
    cudaEventRecord(evRoot, 0);
    cudaStreamWaitEvent(s1, evRoot, 0);
    k_convw<<<dim3(16, 16, 2),  dim3(32, 8), 0, s1>>>(W1, W2, Wh1, 0);  // W1, W2
    cudaEventRecord(evW12, s1);
    k_convw<<<dim3(16, 16, 16), dim3(32, 8), 0, s1>>>(W1, W2, Wh1, 2);  // Wh1 only
    cudaEventRecord(evWh, s1);

    // main stream: zero + pack/bin
    k_zero<<<1, 32>>>();
    k_prep<<<B_DIM / 4, 256>>>(in, bh2, out);

    // join W1/W2 before first GEMM
    cudaStreamWaitEvent(0, evW12, 0);
    k_mm<<<dim3(B_DIM / 128, 4), 256, DSMEM_BYTES>>>(xh, xl, w1h, b1, l1h, l1l);
    k_mm<<<dim3(B_DIM / 128, 4), 256, DSMEM_BYTES>>>(l1h, l1l, w2h, b2, l2h, l2l);

    // join Wh1 before head
    cudaStreamWaitEvent(0, evWh, 0);
    k_head<<<dim3(128, 4, 16), 256, DSMEM_BYTES>>>(l2h, l2l, whh, bh1, Wh2, out);
}

// round 7
// speedup vs baseline: 5.0989x; 1.5821x over previous
#include <cuda_runtime.h>
#include <cuda_fp16.h>
#include <cstdint>

#define B_DIM 16384
#define K_DIM 512
#define T_DIM 16
#define IN_STRIDE 513
#define STAGE_BYTES 16384
#define DSMEM_BYTES (3 * STAGE_BYTES + 128)

// ---------------- device scratch (single fp16 everywhere) ----------------
__device__ __half g_xh[B_DIM * K_DIM];
__device__ __half g_l1h[B_DIM * K_DIM];
__device__ __half g_l2h[B_DIM * K_DIM];
__device__ __half g_w1h[K_DIM * K_DIM];
__device__ __half g_w2h[K_DIM * K_DIM];
__device__ __half g_whh[T_DIM * K_DIM * K_DIM];
__device__ int g_bins[T_DIM * B_DIM];
__device__ int g_cnt[T_DIM];

// ---------------- PTX helpers (sm_80-compatible) ----------------
__device__ __forceinline__ uint32_t smem_u32(const void* p) {
    uint32_t a;
    asm("{ .reg .u64 t; cvta.to.shared.u64 t, %1; cvt.u32.u64 %0, t; }" : "=r"(a) : "l"(p));
    return a;
}
__device__ __forceinline__ void cp16(uint32_t dst, const void* src) {
    asm volatile("cp.async.cg.shared.global [%0], [%1], 16;" :: "r"(dst), "l"(src));
}
__device__ __forceinline__ void cp_commit() { asm volatile("cp.async.commit_group;"); }
template <int N>
__device__ __forceinline__ void cp_wait() { asm volatile("cp.async.wait_group %0;" :: "n"(N)); }

__device__ __forceinline__ void ldsm4(uint32_t addr, uint32_t& r0, uint32_t& r1,
                                      uint32_t& r2, uint32_t& r3) {
    asm volatile("ldmatrix.sync.aligned.m8n8.x4.shared.b16 {%0,%1,%2,%3}, [%4];"
                 : "=r"(r0), "=r"(r1), "=r"(r2), "=r"(r3) : "r"(addr));
}
__device__ __forceinline__ void mma16816(float* c, uint32_t a0, uint32_t a1, uint32_t a2,
                                         uint32_t a3, uint32_t b0, uint32_t b1) {
    asm volatile(
        "mma.sync.aligned.m16n8k16.row.col.f32.f16.f16.f32 "
        "{%0,%1,%2,%3}, {%4,%5,%6,%7}, {%8,%9}, {%0,%1,%2,%3};"
        : "+f"(c[0]), "+f"(c[1]), "+f"(c[2]), "+f"(c[3])
        : "r"(a0), "r"(a1), "r"(a2), "r"(a3), "r"(b0), "r"(b1));
}

__device__ __forceinline__ uint32_t pack_h2(__half a, __half b) {
    return (uint32_t)__half_as_ushort(a) | ((uint32_t)__half_as_ushort(b) << 16);
}

// XOR swizzle on 16B chunks: row stride 64B
__device__ __forceinline__ uint32_t swz(uint32_t base, uint32_t row, uint32_t ch) {
    return base + row * 64u + ((ch ^ ((row >> 1) & 3u)) << 4);
}

// ---------------- small prep kernels ----------------
__global__ void k_zero() {
    if (threadIdx.x < T_DIM) g_cnt[threadIdx.x] = 0;
}

// vectorized pack: 4 rows/block, 64 threads/row, 8 cols/thread; fp16
__global__ void __launch_bounds__(256) k_prep(const float* __restrict__ in,
                                              const float* __restrict__ bh2,
                                              float* __restrict__ out) {
    int r = blockIdx.x * 4 + (threadIdx.x >> 6);
    int c0 = (threadIdx.x & 63) * 8;
    const float* src = in + (size_t)r * IN_STRIDE + c0;
    float v[8];
#pragma unroll
    for (int i = 0; i < 8; i++) v[i] = src[i];
    uint32_t hp[4];
#pragma unroll
    for (int i = 0; i < 4; i++)
        hp[i] = pack_h2(__float2half(v[2 * i]), __float2half(v[2 * i + 1]));
    size_t o = (size_t)r * K_DIM + c0;
    *(uint4*)(g_xh + o) = make_uint4(hp[0], hp[1], hp[2], hp[3]);
    if ((threadIdx.x & 63) == 0) {
        int t = (int)in[(size_t)r * IN_STRIDE + K_DIM];
        int pos = atomicAdd(&g_cnt[t], 1);
        g_bins[t * B_DIM + pos] = r;
        out[r] = bh2[t];
    }
}

// transpose weights [K,N] fp32 -> [N,K] fp16; zeff: 0 -> W1, 1 -> W2, >=2 -> Wh1[zeff-2]
__global__ void k_convw(const float* __restrict__ W1, const float* __restrict__ W2,
                        const float* __restrict__ Wh1, int zbase) {
    __shared__ float tile[32][33];
    int z = blockIdx.z + zbase;
    const float* Wm;
    __half* hi;
    size_t obase;
    if (z == 0)      { Wm = W1; hi = g_w1h; obase = 0; }
    else if (z == 1) { Wm = W2; hi = g_w2h; obase = 0; }
    else {
        int mat = z - 2;
        Wm = Wh1 + (size_t)mat * K_DIM * K_DIM;
        hi = g_whh;
        obase = (size_t)mat * K_DIM * K_DIM;
    }
    int k0 = blockIdx.x * 32, n0 = blockIdx.y * 32;
    for (int ky = threadIdx.y; ky < 32; ky += 8)
        tile[ky][threadIdx.x] = Wm[(size_t)(k0 + ky) * K_DIM + n0 + threadIdx.x];
    __syncthreads();
    for (int ny = threadIdx.y; ny < 32; ny += 8) {
        float v = tile[threadIdx.x][ny];
        hi[obase + (size_t)(n0 + ny) * K_DIM + k0 + threadIdx.x] = __float2half(v);
    }
}

// ---------------- tile loads: 2 sub-tiles (A, W), each 128x32 fp16 ----------------
__device__ __forceinline__ void issue_chunk(
    uint32_t sbuf, int stage, int k0, const int* __restrict__ rows_s, int bn0,
    const __half* __restrict__ A, const __half* __restrict__ Bw, int tid) {
    uint32_t sb = sbuf + (uint32_t)stage * (uint32_t)STAGE_BYTES;
#pragma unroll
    for (int i = 0; i < 4; i++) {
        int idx = tid + i * 256;
        int tile = idx >> 9, w = idx & 511, row = w >> 2, ch = w & 3;
        const __half* src = tile ? Bw : A;
        int gr = tile ? (bn0 + row) : rows_s[row];
        cp16(swz(sb + (uint32_t)tile * 8192u, (uint32_t)row, (uint32_t)ch),
             src + (size_t)gr * K_DIM + k0 + ch * 8);
    }
    cp_commit();
}

// ---------------- per-chunk MMA: single fp16 pass ----------------
__device__ __forceinline__ void compute_chunk(float acc[4][4][4], uint32_t sbuf, int stage,
                                              int lane, int wm, int wn) {
    uint32_t sb = sbuf + (uint32_t)stage * (uint32_t)STAGE_BYTES;
    uint32_t A_t = sb, B_t = sb + 8192u;
    uint32_t lrow = (uint32_t)(lane & 15);
    uint32_t lsel = (uint32_t)(lane >> 4);
#pragma unroll
    for (int kk = 0; kk < 2; kk++) {
        uint32_t ch = (uint32_t)(kk * 2) + lsel;
        uint32_t ah[4][4], bb[2][4];
#pragma unroll
        for (int im = 0; im < 4; im++)
            ldsm4(swz(A_t, (uint32_t)(wm * 64 + im * 16) + lrow, ch),
                  ah[im][0], ah[im][1], ah[im][2], ah[im][3]);
#pragma unroll
        for (int jn = 0; jn < 2; jn++)
            ldsm4(swz(B_t, (uint32_t)(wn * 32 + jn * 16) + lrow, ch),
                  bb[jn][0], bb[jn][1], bb[jn][2], bb[jn][3]);
#pragma unroll
        for (int im = 0; im < 4; im++)
#pragma unroll
            for (int j = 0; j < 4; j++)
                mma16816(acc[im][j], ah[im][0], ah[im][1], ah[im][2], ah[im][3],
                         bb[j >> 1][j & 1], bb[j >> 1][(j & 1) + 2]);
    }
}

// 3-stage pipeline, one barrier per iteration.
__device__ __forceinline__ void mma_mainloop(
    float acc[4][4][4], uint32_t sbuf, const int* __restrict__ rows_s, int bn0,
    const __half* __restrict__ A, const __half* __restrict__ Bw,
    int tid, int lane, int wm, int wn) {
    issue_chunk(sbuf, 0, 0, rows_s, bn0, A, Bw, tid);
    issue_chunk(sbuf, 1, 32, rows_s, bn0, A, Bw, tid);
    int stage = 0;
#pragma unroll 1
    for (int c = 0; c < 16; c++) {
        if (c >= 14) cp_wait<0>(); else cp_wait<1>();
        __syncthreads();
        if (c + 2 < 16) {
            int ns = stage + 2; if (ns >= 3) ns -= 3;
            issue_chunk(sbuf, ns, (c + 2) * 32, rows_s, bn0, A, Bw, tid);
        }
        compute_chunk(acc, sbuf, stage, lane, wm, wn);
        if (++stage == 3) stage = 0;
    }
}

// ---------------- GEMM + bias + relu -> fp16 ----------------
__global__ void __launch_bounds__(256) k_mm(
    const __half* __restrict__ A, const __half* __restrict__ Bw,
    const float* __restrict__ bias, __half* __restrict__ C) {
    extern __shared__ char dsmem[];
    __shared__ int rows_s[128];
    __shared__ float sbias[128];
    uint32_t sbuf = (smem_u32(dsmem) + 127u) & ~127u;

    int tid = threadIdx.x, lane = tid & 31, wid = tid >> 5;
    int wm = wid & 1, wn = wid >> 1;
    int m0 = blockIdx.x * 128, n0 = blockIdx.y * 128;

    if (tid < 128) { rows_s[tid] = m0 + tid; sbias[tid] = bias[n0 + tid]; }
    __syncthreads();

    float acc[4][4][4];
#pragma unroll
    for (int a = 0; a < 4; a++)
#pragma unroll
        for (int b = 0; b < 4; b++)
#pragma unroll
            for (int d = 0; d < 4; d++) acc[a][b][d] = 0.f;

    mma_mainloop(acc, sbuf, rows_s, n0, A, Bw, tid, lane, wm, wn);

#pragma unroll
    for (int im = 0; im < 4; im++) {
        int r0 = m0 + wm * 64 + im * 16 + (lane >> 2);
#pragma unroll
        for (int j = 0; j < 4; j++) {
            int nloc = wn * 32 + j * 8 + (lane & 3) * 2;
            float v0 = fmaxf(acc[im][j][0] + sbias[nloc],     0.f);
            float v1 = fmaxf(acc[im][j][1] + sbias[nloc + 1], 0.f);
            float v2 = fmaxf(acc[im][j][2] + sbias[nloc],     0.f);
            float v3 = fmaxf(acc[im][j][3] + sbias[nloc + 1], 0.f);
            size_t o0 = (size_t)r0 * K_DIM + n0 + nloc;
            size_t o1 = (size_t)(r0 + 8) * K_DIM + n0 + nloc;
            *(uint32_t*)(C + o0) = pack_h2(__float2half(v0), __float2half(v1));
            *(uint32_t*)(C + o1) = pack_h2(__float2half(v2), __float2half(v3));
        }
    }
}

// ---------------- head: gathered GEMM + relu + dot(Wh2) reduce ----------------
__global__ void __launch_bounds__(256) k_head(
    const __half* __restrict__ l2h, const __half* __restrict__ whh,
    const float* __restrict__ bh1, const float* __restrict__ Wh2,
    float* __restrict__ out) {
    int t = blockIdx.z;
    int cnt = g_cnt[t];
    int tile = blockIdx.x;
    if (tile * 128 >= cnt) return;
    int n0 = blockIdx.y * 128;

    extern __shared__ char dsmem[];
    __shared__ int rows_s[128];
    __shared__ float sbh1[128];
    __shared__ float swh2[128];
    uint32_t sbuf = (smem_u32(dsmem) + 127u) & ~127u;

    int tid = threadIdx.x, lane = tid & 31, wid = tid >> 5;
    int wm = wid & 1, wn = wid >> 1;

    if (tid < 128) {
        int idx = tile * 128 + tid;
        rows_s[tid] = g_bins[t * B_DIM + (idx < cnt ? idx : cnt - 1)];
        sbh1[tid] = bh1[t * K_DIM + n0 + tid];
        swh2[tid] = Wh2[t * K_DIM + n0 + tid];
    }
    __syncthreads();

    float acc[4][4][4];
#pragma unroll
    for (int a = 0; a < 4; a++)
#pragma unroll
        for (int b = 0; b < 4; b++)
#pragma unroll
            for (int d = 0; d < 4; d++) acc[a][b][d] = 0.f;

    mma_mainloop(acc, sbuf, rows_s, n0, l2h,
                 whh + (size_t)t * K_DIM * K_DIM, tid, lane, wm, wn);

#pragma unroll
    for (int im = 0; im < 4; im++) {
        float p0 = 0.f, p1 = 0.f;
#pragma unroll
        for (int j = 0; j < 4; j++) {
            int nloc = wn * 32 + j * 8 + (lane & 3) * 2;
            float w0 = swh2[nloc], w1 = swh2[nloc + 1];
            float q0 = sbh1[nloc], q1 = sbh1[nloc + 1];
            p0 = fmaf(fmaxf(acc[im][j][0] + q0, 0.f), w0, p0);
            p0 = fmaf(fmaxf(acc[im][j][1] + q1, 0.f), w1, p0);
            p1 = fmaf(fmaxf(acc[im][j][2] + q0, 0.f), w0, p1);
            p1 = fmaf(fmaxf(acc[im][j][3] + q1, 0.f), w1, p1);
        }
        p0 += __shfl_xor_sync(0xffffffffu, p0, 1);
        p0 += __shfl_xor_sync(0xffffffffu, p0, 2);
        p1 += __shfl_xor_sync(0xffffffffu, p1, 1);
        p1 += __shfl_xor_sync(0xffffffffu, p1, 2);
        if ((lane & 3) == 0) {
            int rl0 = wm * 64 + im * 16 + (lane >> 2);
            int rl1 = rl0 + 8;
            if (tile * 128 + rl0 < cnt) atomicAdd(&out[rows_s[rl0]], p0);
            if (tile * 128 + rl1 < cnt) atomicAdd(&out[rows_s[rl1]], p1);
        }
    }
}

// ---------------- launch ----------------
extern "C" void kernel_launch(void* const* d_in, const int* in_sizes, int n_in,
                              void* d_out, int out_size) {
    const float* in  = (const float*)d_in[0];
    const float* W1  = (const float*)d_in[1];
    const float* b1  = (const float*)d_in[2];
    const float* W2  = (const float*)d_in[3];
    const float* b2  = (const float*)d_in[4];
    const float* Wh1 = (const float*)d_in[5];
    const float* bh1 = (const float*)d_in[6];
    const float* Wh2 = (const float*)d_in[7];
    const float* bh2 = (const float*)d_in[8];
    float* out = (float*)d_out;

    static cudaStream_t s1 = nullptr;
    static cudaEvent_t evRoot = nullptr, evW12 = nullptr, evWh = nullptr;
    if (!s1) {
        cudaStreamCreateWithFlags(&s1, cudaStreamNonBlocking);
        cudaEventCreateWithFlags(&evRoot, cudaEventDisableTiming);
        cudaEventCreateWithFlags(&evW12, cudaEventDisableTiming);
        cudaEventCreateWithFlags(&evWh, cudaEventDisableTiming);
        cudaFuncSetAttribute(k_mm,   cudaFuncAttributeMaxDynamicSharedMemorySize, DSMEM_BYTES);
        cudaFuncSetAttribute(k_head, cudaFuncAttributeMaxDynamicSharedMemorySize, DSMEM_BYTES);
    }

    __half *xh, *l1h, *l2h, *w1h, *w2h, *whh;
    cudaGetSymbolAddress((void**)&xh,  g_xh);
    cudaGetSymbolAddress((void**)&l1h, g_l1h);
    cudaGetSymbolAddress((void**)&l2h, g_l2h);
    cudaGetSymbolAddress((void**)&w1h, g_w1h);
    cudaGetSymbolAddress((void**)&w2h, g_w2h);
    cudaGetSymbolAddress((void**)&whh, g_whh);

    // fork: weight conversion on side stream (W1/W2 first, then Wh1)
    cudaEventRecord(evRoot, 0);
    cudaStreamWaitEvent(s1, evRoot, 0);
    k_convw<<<dim3(16, 16, 2),  dim3(32, 8), 0, s1>>>(W1, W2, Wh1, 0);  // W1, W2
    cudaEventRecord(evW12, s1);
    k_convw<<<dim3(16, 16, 16), dim3(32, 8), 0, s1>>>(W1, W2, Wh1, 2);  // Wh1 only
    cudaEventRecord(evWh, s1);

    // main stream: zero + pack/bin
    k_zero<<<1, 32>>>();
    k_prep<<<B_DIM / 4, 256>>>(in, bh2, out);

    // join W1/W2 before first GEMM
    cudaStreamWaitEvent(0, evW12, 0);
    k_mm<<<dim3(B_DIM / 128, 4), 256, DSMEM_BYTES>>>(xh, w1h, b1, l1h);
    k_mm<<<dim3(B_DIM / 128, 4), 256, DSMEM_BYTES>>>(l1h, w2h, b2, l2h);

    // join Wh1 before head
    cudaStreamWaitEvent(0, evWh, 0);
    k_head<<<dim3(128, 4, 16), 256, DSMEM_BYTES>>>(l2h, whh, bh1, Wh2, out);
}